// round 1
// baseline (speedup 1.0000x reference)
#include <cuda_runtime.h>
#include <math.h>

#define BB 4
#define CC 192
#define HH 128
#define WW 128
#define HWH (HH*WW)          // 16384
#define C3 576
#define HID 384
#define HEADS 6
#define CP 32
#define NSPLIT 8

// ---------------- scratch (static device globals; allocation-free) ------------
__device__ float g_x1  [BB*CC*HWH];
__device__ float g_qkv1[BB*C3*HWH];
__device__ float g_qkv2[BB*C3*HWH];
__device__ float g_invn[BB*2*CC];
__device__ float g_part[NSPLIT*BB*HEADS*CP*CP];
__device__ float g_attn[BB*HEADS*CP*CP];
__device__ float g_av  [BB*CC*HWH];
__device__ float g_x2  [BB*CC*HWH];
__device__ float g_xn  [BB*CC*HWH];
__device__ float g_h1  [BB*HID*HWH];
__device__ float g_y4  [BB*CC*HWH];
__device__ float g_gate[BB*HWH];

__device__ __forceinline__ float gelu_exact(float x) {
    return 0.5f * x * (1.0f + erff(x * 0.70710678118654752f));
}

// ---------------- LayerNorm over channel dim, per pixel ----------------------
__global__ __launch_bounds__(256) void ln_kernel(
    const float* __restrict__ x, const float* __restrict__ g,
    const float* __restrict__ bta, float* __restrict__ out)
{
    int b = blockIdx.y;
    int p = blockIdx.x * 256 + threadIdx.x;
    const float* xp = x + (size_t)b * CC * HWH + p;
    float s = 0.f, ss = 0.f;
    #pragma unroll 4
    for (int c = 0; c < CC; c++) {
        float v = xp[(size_t)c * HWH];
        s += v; ss += v * v;
    }
    float mean = s * (1.0f / CC);
    float var  = ss * (1.0f / CC) - mean * mean;
    float inv  = rsqrtf(var + 1e-5f);
    float* op = out + (size_t)b * CC * HWH + p;
    #pragma unroll 4
    for (int c = 0; c < CC; c++) {
        float v = xp[(size_t)c * HWH];
        op[(size_t)c * HWH] = (v - mean) * inv * g[c] + bta[c];
    }
}

// ---------------- SGEMM: C[M,N] = A[M,K] * B[K,N], per-batch on z ------------
// EPI: 0 = plain, 1 = +bias then GELU, 2 = +residual
template<int EPI>
__global__ __launch_bounds__(256) void sgemm_kernel(
    const float* __restrict__ A, const float* __restrict__ Bm,
    const float* __restrict__ bias, const float* __restrict__ res,
    float* __restrict__ Cm, int M, int N, int K)
{
    __shared__ float As[16][64];
    __shared__ float Bs[16][128];
    const int tid = threadIdx.x;
    const int n0 = blockIdx.x * 128;
    const int m0 = blockIdx.y * 64;
    const float* Bb = Bm + (size_t)blockIdx.z * K * N;
    float* Cb = Cm + (size_t)blockIdx.z * M * N;
    const float* Rb = (EPI == 2) ? (res + (size_t)blockIdx.z * M * N) : nullptr;

    const int am = tid >> 2;           // 0..63
    const int ak = (tid & 3) << 2;     // 0,4,8,12
    const int tm = tid >> 5;           // 0..7
    const int tn = tid & 31;           // 0..31

    float acc[8][4];
    #pragma unroll
    for (int i = 0; i < 8; i++)
        #pragma unroll
        for (int j = 0; j < 4; j++) acc[i][j] = 0.f;

    for (int k0 = 0; k0 < K; k0 += 16) {
        float4 av = *(const float4*)(A + (size_t)(m0 + am) * K + k0 + ak);
        As[ak + 0][am] = av.x;
        As[ak + 1][am] = av.y;
        As[ak + 2][am] = av.z;
        As[ak + 3][am] = av.w;
        #pragma unroll
        for (int l = 0; l < 2; l++) {
            int v  = tid + l * 256;
            int kb = v >> 5;
            int nb = (v & 31) << 2;
            *(float4*)&Bs[kb][nb] =
                *(const float4*)(Bb + (size_t)(k0 + kb) * N + n0 + nb);
        }
        __syncthreads();
        #pragma unroll
        for (int kk = 0; kk < 16; kk++) {
            float4 a0 = *(const float4*)&As[kk][tm << 3];
            float4 a1 = *(const float4*)&As[kk][(tm << 3) + 4];
            float4 bv = *(const float4*)&Bs[kk][tn << 2];
            float a[8] = {a0.x, a0.y, a0.z, a0.w, a1.x, a1.y, a1.z, a1.w};
            float bb[4] = {bv.x, bv.y, bv.z, bv.w};
            #pragma unroll
            for (int i = 0; i < 8; i++)
                #pragma unroll
                for (int j = 0; j < 4; j++)
                    acc[i][j] = fmaf(a[i], bb[j], acc[i][j]);
        }
        __syncthreads();
    }

    #pragma unroll
    for (int i = 0; i < 8; i++) {
        int row = m0 + (tm << 3) + i;
        float bsv = (EPI == 1) ? bias[row] : 0.f;
        #pragma unroll
        for (int j = 0; j < 4; j++) {
            int col = n0 + (tn << 2) + j;
            float v = acc[i][j];
            if (EPI == 1) { v += bsv; v = gelu_exact(v); }
            else if (EPI == 2) { v += Rb[(size_t)row * N + col]; }
            Cb[(size_t)row * N + col] = v;
        }
    }
}

// ---------------- depthwise 3x3, pad 1 ---------------------------------------
__global__ __launch_bounds__(256) void dwconv_kernel(
    const float* __restrict__ in, const float* __restrict__ w,
    float* __restrict__ out)
{
    int p  = blockIdx.x * 256 + threadIdx.x;       // 0..HW-1
    int bc = blockIdx.y;                            // 0..B*C3-1
    int c  = bc % C3;
    int y  = p >> 7;     // /128
    int x0 = p & 127;
    const float* ip = in + (size_t)bc * HWH;
    const float* wp = w + c * 9;
    float acc = 0.f;
    #pragma unroll
    for (int ky = 0; ky < 3; ky++) {
        int yy = y + ky - 1;
        if (yy < 0 || yy >= HH) continue;
        #pragma unroll
        for (int kx = 0; kx < 3; kx++) {
            int xx = x0 + kx - 1;
            if (xx < 0 || xx >= WW) continue;
            acc += wp[ky * 3 + kx] * ip[yy * WW + xx];
        }
    }
    out[(size_t)bc * HWH + p] = acc;
}

// ---------------- per-row inverse L2 norm for q,k (rows of length HW) --------
__global__ __launch_bounds__(256) void rownorm_kernel(
    const float* __restrict__ qkv, float* __restrict__ invn)
{
    int b = blockIdx.x / 384;     // channel index c in [0,384): q then k
    int c = blockIdx.x % 384;
    const float* row = qkv + ((size_t)b * C3 + c) * HWH;
    float ss = 0.f;
    for (int i = threadIdx.x; i < HWH; i += 256) {
        float v = row[i];
        ss += v * v;
    }
    __shared__ float red[256];
    red[threadIdx.x] = ss;
    __syncthreads();
    for (int s = 128; s > 0; s >>= 1) {
        if (threadIdx.x < s) red[threadIdx.x] += red[threadIdx.x + s];
        __syncthreads();
    }
    if (threadIdx.x == 0) {
        float n = sqrtf(red[0]);
        invn[blockIdx.x] = 1.0f / fmaxf(n, 1e-12f);
    }
}

// ---------------- attn partial = q k^T over split-n (deterministic) ----------
__global__ __launch_bounds__(256) void qk_kernel(
    const float* __restrict__ qkv, const float* __restrict__ invn,
    const float* __restrict__ temp, float* __restrict__ part)
{
    int bh = blockIdx.x;                 // b*6+hd
    int b = bh / HEADS, hd = bh % HEADS;
    const float* q = qkv + ((size_t)b * C3 + hd * CP) * HWH;
    const float* k = qkv + ((size_t)b * C3 + CC + hd * CP) * HWH;
    __shared__ float Qs[32][65];
    __shared__ float Ks[32][65];
    const int n0 = blockIdx.y * (HWH / NSPLIT);
    float acc[4] = {0.f, 0.f, 0.f, 0.f};
    const int c = threadIdx.x & 31;
    const int dbase = (threadIdx.x >> 5) * 4;
    for (int t = 0; t < HWH / NSPLIT; t += 64) {
        for (int i = threadIdx.x; i < 32 * 64; i += 256) {
            int r = i >> 6, col = i & 63;
            Qs[r][col] = q[(size_t)r * HWH + n0 + t + col];
            Ks[r][col] = k[(size_t)r * HWH + n0 + t + col];
        }
        __syncthreads();
        #pragma unroll 8
        for (int n = 0; n < 64; n++) {
            float qv = Qs[c][n];
            acc[0] = fmaf(qv, Ks[dbase + 0][n], acc[0]);
            acc[1] = fmaf(qv, Ks[dbase + 1][n], acc[1]);
            acc[2] = fmaf(qv, Ks[dbase + 2][n], acc[2]);
            acc[3] = fmaf(qv, Ks[dbase + 3][n], acc[3]);
        }
        __syncthreads();
    }
    float iq = invn[b * 384 + hd * CP + c];
    float tp = temp[hd];
    #pragma unroll
    for (int j = 0; j < 4; j++) {
        int d = dbase + j;
        float ik = invn[b * 384 + CC + hd * CP + d];
        part[((size_t)blockIdx.y * (BB * HEADS) + bh) * 1024 + c * 32 + d]
            = acc[j] * iq * ik * tp;
    }
}

// ---------------- reduce partials + 3x3 conv over heads + softmax ------------
__global__ __launch_bounds__(256) void headconv_softmax_kernel(
    const float* __restrict__ part, const float* __restrict__ w_head,
    float* __restrict__ attnF)
{
    int b = blockIdx.x;
    __shared__ float A[HEADS * 1024];
    __shared__ float wsh[HEADS * HEADS * 9];
    int tid = threadIdx.x;
    if (tid < HEADS * HEADS * 9) wsh[tid] = w_head[tid];
    for (int i = tid; i < HEADS * 1024; i += 256) {
        int hd = i >> 10, rest = i & 1023;
        float s = 0.f;
        #pragma unroll
        for (int sp = 0; sp < NSPLIT; sp++)
            s += part[((size_t)sp * (BB * HEADS) + b * HEADS + hd) * 1024 + rest];
        A[i] = s;
    }
    __syncthreads();
    float cv[24];
    #pragma unroll
    for (int r = 0; r < 24; r++) {
        int i  = tid * 24 + r;
        int ho = i >> 10;
        int yx = i & 1023;
        int y  = yx >> 5, x = yx & 31;
        float s = 0.f;
        for (int hi = 0; hi < HEADS; hi++) {
            const float* Ah = &A[hi * 1024];
            #pragma unroll
            for (int ky = 0; ky < 3; ky++) {
                int yy = y + ky - 1;
                if (yy < 0 || yy > 31) continue;
                #pragma unroll
                for (int kx = 0; kx < 3; kx++) {
                    int xx = x + kx - 1;
                    if (xx < 0 || xx > 31) continue;
                    s += wsh[((ho * HEADS + hi) * 3 + ky) * 3 + kx] * Ah[yy * 32 + xx];
                }
            }
        }
        cv[r] = s;
    }
    __syncthreads();
    #pragma unroll
    for (int r = 0; r < 24; r++) A[tid * 24 + r] = cv[r];
    __syncthreads();
    if (tid < HEADS * 32) {          // 192 rows of 32
        float* row = &A[tid * 32];
        float mx = -1e30f;
        for (int j = 0; j < 32; j++) mx = fmaxf(mx, row[j]);
        float sum = 0.f, e[32];
        for (int j = 0; j < 32; j++) { e[j] = expf(row[j] - mx); sum += e[j]; }
        float inv = 1.0f / sum;
        float* o = attnF + (size_t)b * (HEADS * 1024) + tid * 32;
        for (int j = 0; j < 32; j++) o[j] = e[j] * inv;
    }
}

// ---------------- out = attn @ v ----------------------------------------------
__global__ __launch_bounds__(256) void av_kernel(
    const float* __restrict__ attn, const float* __restrict__ qkv,
    float* __restrict__ out)
{
    int bh = blockIdx.y;
    int b = bh / HEADS, hd = bh % HEADS;
    __shared__ float As[32][32];
    for (int i = threadIdx.x; i < 1024; i += 256)
        ((float*)As)[i] = attn[(size_t)bh * 1024 + i];
    __syncthreads();
    int n = blockIdx.x * 256 + threadIdx.x;
    const float* v = qkv + ((size_t)b * C3 + 2 * CC + hd * CP) * HWH + n;
    float vv[32];
    #pragma unroll
    for (int d = 0; d < 32; d++) vv[d] = v[(size_t)d * HWH];
    float* op = out + ((size_t)b * CC + hd * CP) * HWH + n;
    #pragma unroll
    for (int c = 0; c < 32; c++) {
        float s = 0.f;
        #pragma unroll
        for (int d = 0; d < 32; d++) s = fmaf(As[c][d], vv[d], s);
        op[(size_t)c * HWH] = s;
    }
}

// ---------------- spatial gate: sigmoid(conv3x3 over all 192 channels) -------
__global__ __launch_bounds__(256) void gate_kernel(
    const float* __restrict__ y4, const float* __restrict__ w_sa,
    const float* __restrict__ b_sa, float* __restrict__ gate)
{
    __shared__ float tile[18][18];
    __shared__ float ws[CC * 9];
    int bx = blockIdx.x & 7;
    int by = (blockIdx.x >> 3) & 7;
    int b  = blockIdx.x >> 6;
    int tx = threadIdx.x & 15, ty = threadIdx.x >> 4;
    for (int i = threadIdx.x; i < CC * 9; i += 256) ws[i] = w_sa[i];
    float acc = 0.f;
    for (int c = 0; c < CC; c++) {
        const float* ip = y4 + ((size_t)b * CC + c) * HWH;
        for (int i = threadIdx.x; i < 18 * 18; i += 256) {
            int ly = i / 18, lx = i % 18;
            int gy = by * 16 + ly - 1, gx = bx * 16 + lx - 1;
            tile[ly][lx] = (gy >= 0 && gy < HH && gx >= 0 && gx < WW)
                               ? ip[gy * WW + gx] : 0.f;
        }
        __syncthreads();
        const float* wp = &ws[c * 9];
        #pragma unroll
        for (int ky = 0; ky < 3; ky++)
            #pragma unroll
            for (int kx = 0; kx < 3; kx++)
                acc = fmaf(wp[ky * 3 + kx], tile[ty + ky][tx + kx], acc);
        __syncthreads();
    }
    int oy = by * 16 + ty, ox = bx * 16 + tx;
    gate[(size_t)b * HWH + oy * WW + ox] =
        1.0f / (1.0f + expf(-(acc + b_sa[0])));
}

// ---------------- final: out = x2 + y4 * gate ---------------------------------
__global__ __launch_bounds__(256) void final_kernel(
    const float* __restrict__ x2, const float* __restrict__ y4,
    const float* __restrict__ gate, float* __restrict__ out)
{
    int i4 = blockIdx.x * 256 + threadIdx.x;   // float4 index
    int elem = i4 * 4;
    int b = elem / (CC * HWH);
    int p = elem % HWH;
    float4 a = ((const float4*)x2)[i4];
    float4 y = ((const float4*)y4)[i4];
    float4 g = ((const float4*)gate)[(size_t)b * (HWH / 4) + (p >> 2)];
    float4 r;
    r.x = a.x + y.x * g.x;
    r.y = a.y + y.y * g.y;
    r.z = a.z + y.z * g.z;
    r.w = a.w + y.w * g.w;
    ((float4*)out)[i4] = r;
}

// =============================================================================
extern "C" void kernel_launch(void* const* d_in, const int* in_sizes, int n_in,
                              void* d_out, int out_size)
{
    const float* x      = (const float*)d_in[0];
    const float* g1     = (const float*)d_in[1];
    const float* b1     = (const float*)d_in[2];
    const float* w_qkv  = (const float*)d_in[3];
    const float* w_dw   = (const float*)d_in[4];
    const float* temp   = (const float*)d_in[5];
    const float* w_head = (const float*)d_in[6];
    const float* w_proj = (const float*)d_in[7];
    const float* g2     = (const float*)d_in[8];
    const float* b2     = (const float*)d_in[9];
    const float* w_fc1  = (const float*)d_in[10];
    const float* b_fc1  = (const float*)d_in[11];
    const float* w_fc2  = (const float*)d_in[12];
    const float* b_fc2  = (const float*)d_in[13];
    const float* w_sa   = (const float*)d_in[14];
    const float* b_sa   = (const float*)d_in[15];
    float* out = (float*)d_out;

    float *p_x1, *p_qkv1, *p_qkv2, *p_invn, *p_part, *p_attn, *p_av,
          *p_x2, *p_xn, *p_h1, *p_y4, *p_gate;
    cudaGetSymbolAddress((void**)&p_x1,   g_x1);
    cudaGetSymbolAddress((void**)&p_qkv1, g_qkv1);
    cudaGetSymbolAddress((void**)&p_qkv2, g_qkv2);
    cudaGetSymbolAddress((void**)&p_invn, g_invn);
    cudaGetSymbolAddress((void**)&p_part, g_part);
    cudaGetSymbolAddress((void**)&p_attn, g_attn);
    cudaGetSymbolAddress((void**)&p_av,   g_av);
    cudaGetSymbolAddress((void**)&p_x2,   g_x2);
    cudaGetSymbolAddress((void**)&p_xn,   g_xn);
    cudaGetSymbolAddress((void**)&p_h1,   g_h1);
    cudaGetSymbolAddress((void**)&p_y4,   g_y4);
    cudaGetSymbolAddress((void**)&p_gate, g_gate);

    // 1) LN1: x -> x1
    ln_kernel<<<dim3(HWH / 256, BB), 256>>>(x, g1, b1, p_x1);

    // 2) qkv 1x1 conv: [576,192] @ x1 -> qkv1
    sgemm_kernel<0><<<dim3(HWH / 128, C3 / 64, BB), 256>>>(
        w_qkv, p_x1, nullptr, nullptr, p_qkv1, C3, HWH, CC);

    // 3) depthwise 3x3: qkv1 -> qkv2
    dwconv_kernel<<<dim3(HWH / 256, BB * C3), 256>>>(p_qkv1, w_dw, p_qkv2);

    // 4) q,k row inverse norms
    rownorm_kernel<<<BB * 2 * CC, 256>>>(p_qkv2, p_invn);

    // 5) attn partials (split-K, deterministic)
    qk_kernel<<<dim3(BB * HEADS, NSPLIT), 256>>>(p_qkv2, p_invn, temp, p_part);

    // 6) reduce + head conv + softmax
    headconv_softmax_kernel<<<BB, 256>>>(p_part, w_head, p_attn);

    // 7) attn @ v
    av_kernel<<<dim3(HWH / 256, BB * HEADS), 256>>>(p_attn, p_qkv2, p_av);

    // 8) proj 1x1 + residual x1 -> x2
    sgemm_kernel<2><<<dim3(HWH / 128, CC / 64, BB), 256>>>(
        w_proj, p_av, nullptr, p_x1, p_x2, CC, HWH, CC);

    // 9) LN2: x2 -> xn
    ln_kernel<<<dim3(HWH / 256, BB), 256>>>(p_x2, g2, b2, p_xn);

    // 10) fc1 + bias + gelu -> h1
    sgemm_kernel<1><<<dim3(HWH / 128, HID / 64, BB), 256>>>(
        w_fc1, p_xn, b_fc1, nullptr, p_h1, HID, HWH, CC);

    // 11) fc2 + bias + gelu -> y4
    sgemm_kernel<1><<<dim3(HWH / 128, CC / 64, BB), 256>>>(
        w_fc2, p_h1, b_fc2, nullptr, p_y4, CC, HWH, HID);

    // 12) spatial gate
    gate_kernel<<<BB * 64, 256>>>(p_y4, w_sa, b_sa, p_gate);

    // 13) final: out = x2 + y4*gate
    final_kernel<<<(BB * CC * HWH / 4) / 256, 256>>>(p_x2, p_y4, p_gate, out);

    (void)in_sizes; (void)n_in; (void)out_size;
}

// round 2
// speedup vs baseline: 1.0035x; 1.0035x over previous
#include <cuda_runtime.h>
#include <math.h>

#define BB 4
#define CC 192
#define HH 128
#define WW 128
#define HWH (HH*WW)          // 16384
#define C3 576
#define HID 384
#define HEADS 6
#define CP 32
#define NSPLIT 8

// ---------------- scratch (static device globals; allocation-free) ------------
__device__ float g_x1  [BB*CC*HWH];
__device__ float g_qkv1[BB*C3*HWH];
__device__ float g_qkv2[BB*C3*HWH];
__device__ float g_invn[BB*2*CC];
__device__ float g_part[NSPLIT*BB*HEADS*CP*CP];
__device__ float g_attn[BB*HEADS*CP*CP];
__device__ float g_av  [BB*CC*HWH];
__device__ float g_x2  [BB*CC*HWH];
__device__ float g_xn  [BB*CC*HWH];
__device__ float g_h1  [BB*HID*HWH];
__device__ float g_y4  [BB*CC*HWH];
__device__ float g_gate[BB*HWH];

__device__ __forceinline__ float gelu_exact(float x) {
    return 0.5f * x * (1.0f + erff(x * 0.70710678118654752f));
}

// ---------------- LayerNorm over channel dim, per pixel ----------------------
__global__ __launch_bounds__(256) void ln_kernel(
    const float* __restrict__ x, const float* __restrict__ g,
    const float* __restrict__ bta, float* __restrict__ out)
{
    int b = blockIdx.y;
    int p = blockIdx.x * 256 + threadIdx.x;
    const float* xp = x + (size_t)b * CC * HWH + p;
    float s = 0.f, ss = 0.f;
    #pragma unroll 4
    for (int c = 0; c < CC; c++) {
        float v = xp[(size_t)c * HWH];
        s += v; ss += v * v;
    }
    float mean = s * (1.0f / CC);
    float var  = ss * (1.0f / CC) - mean * mean;
    float inv  = rsqrtf(var + 1e-5f);
    float* op = out + (size_t)b * CC * HWH + p;
    #pragma unroll 4
    for (int c = 0; c < CC; c++) {
        float v = xp[(size_t)c * HWH];
        op[(size_t)c * HWH] = (v - mean) * inv * g[c] + bta[c];
    }
}

// ---------------- SGEMM: C[M,N] = A[M,K] * B[K,N], per-batch on z ------------
// EPI: 0 = plain, 1 = +bias then GELU, 2 = +residual
template<int EPI>
__global__ __launch_bounds__(256) void sgemm_kernel(
    const float* __restrict__ A, const float* __restrict__ Bm,
    const float* __restrict__ bias, const float* __restrict__ res,
    float* __restrict__ Cm, int M, int N, int K)
{
    __shared__ float As[16][64];
    __shared__ float Bs[16][128];
    const int tid = threadIdx.x;
    const int n0 = blockIdx.x * 128;
    const int m0 = blockIdx.y * 64;
    const float* Bb = Bm + (size_t)blockIdx.z * K * N;
    float* Cb = Cm + (size_t)blockIdx.z * M * N;
    const float* Rb = (EPI == 2) ? (res + (size_t)blockIdx.z * M * N) : nullptr;

    const int am = tid >> 2;           // 0..63
    const int ak = (tid & 3) << 2;     // 0,4,8,12
    const int tm = tid >> 5;           // 0..7
    const int tn = tid & 31;           // 0..31

    float acc[8][4];
    #pragma unroll
    for (int i = 0; i < 8; i++)
        #pragma unroll
        for (int j = 0; j < 4; j++) acc[i][j] = 0.f;

    for (int k0 = 0; k0 < K; k0 += 16) {
        float4 av = *(const float4*)(A + (size_t)(m0 + am) * K + k0 + ak);
        As[ak + 0][am] = av.x;
        As[ak + 1][am] = av.y;
        As[ak + 2][am] = av.z;
        As[ak + 3][am] = av.w;
        #pragma unroll
        for (int l = 0; l < 2; l++) {
            int v  = tid + l * 256;
            int kb = v >> 5;
            int nb = (v & 31) << 2;
            *(float4*)&Bs[kb][nb] =
                *(const float4*)(Bb + (size_t)(k0 + kb) * N + n0 + nb);
        }
        __syncthreads();
        #pragma unroll
        for (int kk = 0; kk < 16; kk++) {
            float4 a0 = *(const float4*)&As[kk][tm << 3];
            float4 a1 = *(const float4*)&As[kk][(tm << 3) + 4];
            float4 bv = *(const float4*)&Bs[kk][tn << 2];
            float a[8] = {a0.x, a0.y, a0.z, a0.w, a1.x, a1.y, a1.z, a1.w};
            float bb[4] = {bv.x, bv.y, bv.z, bv.w};
            #pragma unroll
            for (int i = 0; i < 8; i++)
                #pragma unroll
                for (int j = 0; j < 4; j++)
                    acc[i][j] = fmaf(a[i], bb[j], acc[i][j]);
        }
        __syncthreads();
    }

    #pragma unroll
    for (int i = 0; i < 8; i++) {
        int row = m0 + (tm << 3) + i;
        float bsv = (EPI == 1) ? bias[row] : 0.f;
        #pragma unroll
        for (int j = 0; j < 4; j++) {
            int col = n0 + (tn << 2) + j;
            float v = acc[i][j];
            if (EPI == 1) { v += bsv; v = gelu_exact(v); }
            else if (EPI == 2) { v += Rb[(size_t)row * N + col]; }
            Cb[(size_t)row * N + col] = v;
        }
    }
}

// ---------------- depthwise 3x3, pad 1 ---------------------------------------
__global__ __launch_bounds__(256) void dwconv_kernel(
    const float* __restrict__ in, const float* __restrict__ w,
    float* __restrict__ out)
{
    int p  = blockIdx.x * 256 + threadIdx.x;       // 0..HW-1
    int bc = blockIdx.y;                            // 0..B*C3-1
    int c  = bc % C3;
    int y  = p >> 7;     // /128
    int x0 = p & 127;
    const float* ip = in + (size_t)bc * HWH;
    const float* wp = w + c * 9;
    float acc = 0.f;
    #pragma unroll
    for (int ky = 0; ky < 3; ky++) {
        int yy = y + ky - 1;
        if (yy < 0 || yy >= HH) continue;
        #pragma unroll
        for (int kx = 0; kx < 3; kx++) {
            int xx = x0 + kx - 1;
            if (xx < 0 || xx >= WW) continue;
            acc += wp[ky * 3 + kx] * ip[yy * WW + xx];
        }
    }
    out[(size_t)bc * HWH + p] = acc;
}

// ---------------- per-row inverse L2 norm for q,k (rows of length HW) --------
__global__ __launch_bounds__(256) void rownorm_kernel(
    const float* __restrict__ qkv, float* __restrict__ invn)
{
    int b = blockIdx.x / 384;     // channel index c in [0,384): q then k
    int c = blockIdx.x % 384;
    const float* row = qkv + ((size_t)b * C3 + c) * HWH;
    float ss = 0.f;
    for (int i = threadIdx.x; i < HWH; i += 256) {
        float v = row[i];
        ss += v * v;
    }
    __shared__ float red[256];
    red[threadIdx.x] = ss;
    __syncthreads();
    for (int s = 128; s > 0; s >>= 1) {
        if (threadIdx.x < s) red[threadIdx.x] += red[threadIdx.x + s];
        __syncthreads();
    }
    if (threadIdx.x == 0) {
        float n = sqrtf(red[0]);
        invn[blockIdx.x] = 1.0f / fmaxf(n, 1e-12f);
    }
}

// ---------------- attn partial = q k^T over split-n (deterministic) ----------
__global__ __launch_bounds__(256) void qk_kernel(
    const float* __restrict__ qkv, const float* __restrict__ invn,
    const float* __restrict__ temp, float* __restrict__ part)
{
    int bh = blockIdx.x;                 // b*6+hd
    int b = bh / HEADS, hd = bh % HEADS;
    const float* q = qkv + ((size_t)b * C3 + hd * CP) * HWH;
    const float* k = qkv + ((size_t)b * C3 + CC + hd * CP) * HWH;
    __shared__ float Qs[32][65];
    __shared__ float Ks[32][65];
    const int n0 = blockIdx.y * (HWH / NSPLIT);
    float acc[4] = {0.f, 0.f, 0.f, 0.f};
    const int c = threadIdx.x & 31;
    const int dbase = (threadIdx.x >> 5) * 4;
    for (int t = 0; t < HWH / NSPLIT; t += 64) {
        for (int i = threadIdx.x; i < 32 * 64; i += 256) {
            int r = i >> 6, col = i & 63;
            Qs[r][col] = q[(size_t)r * HWH + n0 + t + col];
            Ks[r][col] = k[(size_t)r * HWH + n0 + t + col];
        }
        __syncthreads();
        #pragma unroll 8
        for (int n = 0; n < 64; n++) {
            float qv = Qs[c][n];
            acc[0] = fmaf(qv, Ks[dbase + 0][n], acc[0]);
            acc[1] = fmaf(qv, Ks[dbase + 1][n], acc[1]);
            acc[2] = fmaf(qv, Ks[dbase + 2][n], acc[2]);
            acc[3] = fmaf(qv, Ks[dbase + 3][n], acc[3]);
        }
        __syncthreads();
    }
    float iq = invn[b * 384 + hd * CP + c];
    float tp = temp[hd];
    #pragma unroll
    for (int j = 0; j < 4; j++) {
        int d = dbase + j;
        float ik = invn[b * 384 + CC + hd * CP + d];
        part[((size_t)blockIdx.y * (BB * HEADS) + bh) * 1024 + c * 32 + d]
            = acc[j] * iq * ik * tp;
    }
}

// ---------------- reduce partials + 3x3 conv over heads + softmax ------------
__global__ __launch_bounds__(256) void headconv_softmax_kernel(
    const float* __restrict__ part, const float* __restrict__ w_head,
    float* __restrict__ attnF)
{
    int b = blockIdx.x;
    __shared__ float A[HEADS * 1024];
    __shared__ float wsh[HEADS * HEADS * 9];
    int tid = threadIdx.x;
    if (tid < HEADS * HEADS * 9) wsh[tid] = w_head[tid];
    for (int i = tid; i < HEADS * 1024; i += 256) {
        int hd = i >> 10, rest = i & 1023;
        float s = 0.f;
        #pragma unroll
        for (int sp = 0; sp < NSPLIT; sp++)
            s += part[((size_t)sp * (BB * HEADS) + b * HEADS + hd) * 1024 + rest];
        A[i] = s;
    }
    __syncthreads();
    float cv[24];
    #pragma unroll
    for (int r = 0; r < 24; r++) {
        int i  = tid * 24 + r;
        int ho = i >> 10;
        int yx = i & 1023;
        int y  = yx >> 5, x = yx & 31;
        float s = 0.f;
        for (int hi = 0; hi < HEADS; hi++) {
            const float* Ah = &A[hi * 1024];
            #pragma unroll
            for (int ky = 0; ky < 3; ky++) {
                int yy = y + ky - 1;
                if (yy < 0 || yy > 31) continue;
                #pragma unroll
                for (int kx = 0; kx < 3; kx++) {
                    int xx = x + kx - 1;
                    if (xx < 0 || xx > 31) continue;
                    s += wsh[((ho * HEADS + hi) * 3 + ky) * 3 + kx] * Ah[yy * 32 + xx];
                }
            }
        }
        cv[r] = s;
    }
    __syncthreads();
    #pragma unroll
    for (int r = 0; r < 24; r++) A[tid * 24 + r] = cv[r];
    __syncthreads();
    if (tid < HEADS * 32) {          // 192 rows of 32
        float* row = &A[tid * 32];
        float mx = -1e30f;
        for (int j = 0; j < 32; j++) mx = fmaxf(mx, row[j]);
        float sum = 0.f, e[32];
        for (int j = 0; j < 32; j++) { e[j] = expf(row[j] - mx); sum += e[j]; }
        float inv = 1.0f / sum;
        float* o = attnF + (size_t)b * (HEADS * 1024) + tid * 32;
        for (int j = 0; j < 32; j++) o[j] = e[j] * inv;
    }
}

// ---------------- out = attn @ v ----------------------------------------------
__global__ __launch_bounds__(256) void av_kernel(
    const float* __restrict__ attn, const float* __restrict__ qkv,
    float* __restrict__ out)
{
    int bh = blockIdx.y;
    int b = bh / HEADS, hd = bh % HEADS;
    __shared__ float As[32][32];
    for (int i = threadIdx.x; i < 1024; i += 256)
        ((float*)As)[i] = attn[(size_t)bh * 1024 + i];
    __syncthreads();
    int n = blockIdx.x * 256 + threadIdx.x;
    const float* v = qkv + ((size_t)b * C3 + 2 * CC + hd * CP) * HWH + n;
    float vv[32];
    #pragma unroll
    for (int d = 0; d < 32; d++) vv[d] = v[(size_t)d * HWH];
    float* op = out + ((size_t)b * CC + hd * CP) * HWH + n;
    #pragma unroll
    for (int c = 0; c < 32; c++) {
        float s = 0.f;
        #pragma unroll
        for (int d = 0; d < 32; d++) s = fmaf(As[c][d], vv[d], s);
        op[(size_t)c * HWH] = s;
    }
}

// ---------------- spatial gate: sigmoid(conv3x3 over all 192 channels) -------
__global__ __launch_bounds__(256) void gate_kernel(
    const float* __restrict__ y4, const float* __restrict__ w_sa,
    const float* __restrict__ b_sa, float* __restrict__ gate)
{
    __shared__ float tile[18][18];
    __shared__ float ws[CC * 9];
    int bx = blockIdx.x & 7;
    int by = (blockIdx.x >> 3) & 7;
    int b  = blockIdx.x >> 6;
    int tx = threadIdx.x & 15, ty = threadIdx.x >> 4;
    for (int i = threadIdx.x; i < CC * 9; i += 256) ws[i] = w_sa[i];
    float acc = 0.f;
    for (int c = 0; c < CC; c++) {
        const float* ip = y4 + ((size_t)b * CC + c) * HWH;
        for (int i = threadIdx.x; i < 18 * 18; i += 256) {
            int ly = i / 18, lx = i % 18;
            int gy = by * 16 + ly - 1, gx = bx * 16 + lx - 1;
            tile[ly][lx] = (gy >= 0 && gy < HH && gx >= 0 && gx < WW)
                               ? ip[gy * WW + gx] : 0.f;
        }
        __syncthreads();
        const float* wp = &ws[c * 9];
        #pragma unroll
        for (int ky = 0; ky < 3; ky++)
            #pragma unroll
            for (int kx = 0; kx < 3; kx++)
                acc = fmaf(wp[ky * 3 + kx], tile[ty + ky][tx + kx], acc);
        __syncthreads();
    }
    int oy = by * 16 + ty, ox = bx * 16 + tx;
    gate[(size_t)b * HWH + oy * WW + ox] =
        1.0f / (1.0f + expf(-(acc + b_sa[0])));
}

// ---------------- final: out = x2 + y4 * gate ---------------------------------
__global__ __launch_bounds__(256) void final_kernel(
    const float* __restrict__ x2, const float* __restrict__ y4,
    const float* __restrict__ gate, float* __restrict__ out)
{
    int i4 = blockIdx.x * 256 + threadIdx.x;   // float4 index
    int elem = i4 * 4;
    int b = elem / (CC * HWH);
    int p = elem % HWH;
    float4 a = ((const float4*)x2)[i4];
    float4 y = ((const float4*)y4)[i4];
    float4 g = ((const float4*)gate)[(size_t)b * (HWH / 4) + (p >> 2)];
    float4 r;
    r.x = a.x + y.x * g.x;
    r.y = a.y + y.y * g.y;
    r.z = a.z + y.z * g.z;
    r.w = a.w + y.w * g.w;
    ((float4*)out)[i4] = r;
}

// =============================================================================
extern "C" void kernel_launch(void* const* d_in, const int* in_sizes, int n_in,
                              void* d_out, int out_size)
{
    const float* x      = (const float*)d_in[0];
    const float* g1     = (const float*)d_in[1];
    const float* b1     = (const float*)d_in[2];
    const float* w_qkv  = (const float*)d_in[3];
    const float* w_dw   = (const float*)d_in[4];
    const float* temp   = (const float*)d_in[5];
    const float* w_head = (const float*)d_in[6];
    const float* w_proj = (const float*)d_in[7];
    const float* g2     = (const float*)d_in[8];
    const float* b2     = (const float*)d_in[9];
    const float* w_fc1  = (const float*)d_in[10];
    const float* b_fc1  = (const float*)d_in[11];
    const float* w_fc2  = (const float*)d_in[12];
    const float* b_fc2  = (const float*)d_in[13];
    const float* w_sa   = (const float*)d_in[14];
    const float* b_sa   = (const float*)d_in[15];
    float* out = (float*)d_out;

    float *p_x1, *p_qkv1, *p_qkv2, *p_invn, *p_part, *p_attn, *p_av,
          *p_x2, *p_xn, *p_h1, *p_y4, *p_gate;
    cudaGetSymbolAddress((void**)&p_x1,   g_x1);
    cudaGetSymbolAddress((void**)&p_qkv1, g_qkv1);
    cudaGetSymbolAddress((void**)&p_qkv2, g_qkv2);
    cudaGetSymbolAddress((void**)&p_invn, g_invn);
    cudaGetSymbolAddress((void**)&p_part, g_part);
    cudaGetSymbolAddress((void**)&p_attn, g_attn);
    cudaGetSymbolAddress((void**)&p_av,   g_av);
    cudaGetSymbolAddress((void**)&p_x2,   g_x2);
    cudaGetSymbolAddress((void**)&p_xn,   g_xn);
    cudaGetSymbolAddress((void**)&p_h1,   g_h1);
    cudaGetSymbolAddress((void**)&p_y4,   g_y4);
    cudaGetSymbolAddress((void**)&p_gate, g_gate);

    // 1) LN1: x -> x1
    ln_kernel<<<dim3(HWH / 256, BB), 256>>>(x, g1, b1, p_x1);

    // 2) qkv 1x1 conv: [576,192] @ x1 -> qkv1
    sgemm_kernel<0><<<dim3(HWH / 128, C3 / 64, BB), 256>>>(
        w_qkv, p_x1, nullptr, nullptr, p_qkv1, C3, HWH, CC);

    // 3) depthwise 3x3: qkv1 -> qkv2
    dwconv_kernel<<<dim3(HWH / 256, BB * C3), 256>>>(p_qkv1, w_dw, p_qkv2);

    // 4) q,k row inverse norms
    rownorm_kernel<<<BB * 2 * CC, 256>>>(p_qkv2, p_invn);

    // 5) attn partials (split-K, deterministic)
    qk_kernel<<<dim3(BB * HEADS, NSPLIT), 256>>>(p_qkv2, p_invn, temp, p_part);

    // 6) reduce + head conv + softmax
    headconv_softmax_kernel<<<BB, 256>>>(p_part, w_head, p_attn);

    // 7) attn @ v
    av_kernel<<<dim3(HWH / 256, BB * HEADS), 256>>>(p_attn, p_qkv2, p_av);

    // 8) proj 1x1 + residual x1 -> x2
    sgemm_kernel<2><<<dim3(HWH / 128, CC / 64, BB), 256>>>(
        w_proj, p_av, nullptr, p_x1, p_x2, CC, HWH, CC);

    // 9) LN2: x2 -> xn
    ln_kernel<<<dim3(HWH / 256, BB), 256>>>(p_x2, g2, b2, p_xn);

    // 10) fc1 + bias + gelu -> h1
    sgemm_kernel<1><<<dim3(HWH / 128, HID / 64, BB), 256>>>(
        w_fc1, p_xn, b_fc1, nullptr, p_h1, HID, HWH, CC);

    // 11) fc2 + bias + gelu -> y4
    sgemm_kernel<1><<<dim3(HWH / 128, CC / 64, BB), 256>>>(
        w_fc2, p_h1, b_fc2, nullptr, p_y4, CC, HWH, HID);

    // 12) spatial gate
    gate_kernel<<<BB * 64, 256>>>(p_y4, w_sa, b_sa, p_gate);

    // 13) final: out = x2 + y4*gate
    final_kernel<<<(BB * CC * HWH / 4) / 256, 256>>>(p_x2, p_y4, p_gate, out);

    (void)in_sizes; (void)n_in; (void)out_size;
}

// round 4
// speedup vs baseline: 1.1256x; 1.1217x over previous
#include <cuda_runtime.h>
#include <cuda_bf16.h>
#include <math.h>
#include <stdint.h>

#define BB 4
#define CC 192
#define HH 128
#define WW 128
#define HWH (HH*WW)          // 16384
#define C3 576
#define HID 384
#define HEADS 6
#define CP 32
#define NSPLIT 8
#define NTOK (BB*HWH)        // 65536

// ---------------- scratch (device globals; allocation-free) -------------------
__device__ float         g_x1  [(size_t)BB*CC*HWH];
__device__ __nv_bfloat16 g_x1s [(size_t)NTOK*2*CC];
__device__ float         g_qkv1[(size_t)BB*C3*HWH];
__device__ float         g_qkv2[(size_t)BB*C3*HWH];
__device__ float         g_invn[BB*2*CC];
__device__ float         g_part[NSPLIT*BB*HEADS*CP*CP];
__device__ float         g_attn[BB*HEADS*CP*CP];
__device__ __nv_bfloat16 g_avs [(size_t)NTOK*2*CC];
__device__ float         g_x2  [(size_t)BB*CC*HWH];
__device__ __nv_bfloat16 g_xns [(size_t)NTOK*2*CC];
__device__ __nv_bfloat16 g_h1s [(size_t)NTOK*2*HID];
__device__ float         g_y4  [(size_t)BB*CC*HWH];
__device__ float         g_gate[NTOK];
__device__ __nv_bfloat16 g_wq  [(size_t)C3 *3*CC];
__device__ __nv_bfloat16 g_wp  [(size_t)CC *3*CC];
__device__ __nv_bfloat16 g_w1  [(size_t)HID*3*CC];
__device__ __nv_bfloat16 g_w2  [(size_t)CC *3*HID];

// ---------------- small helpers ----------------------------------------------
__device__ __forceinline__ float gelu_exact(float x) {
    return 0.5f * x * (1.0f + erff(x * 0.70710678118654752f));
}
__device__ __forceinline__ uint32_t smem_u32(const void* p) {
    uint32_t a;
    asm("{ .reg .u64 t; cvta.to.shared.u64 t, %1; cvt.u32.u64 %0, t; }"
        : "=r"(a) : "l"(p));
    return a;
}
__device__ __forceinline__ void cpa16(uint32_t dst, const void* src) {
    asm volatile("cp.async.cg.shared.global [%0], [%1], 16;" :: "r"(dst), "l"(src) : "memory");
}
__device__ __forceinline__ uint32_t lds32(const __nv_bfloat16* p) {
    return *(const uint32_t*)p;
}
__device__ __forceinline__ void mma16816(float* c, const uint32_t* a, const uint32_t* b) {
    asm volatile(
        "mma.sync.aligned.m16n8k16.row.col.f32.bf16.bf16.f32 "
        "{%0,%1,%2,%3}, {%4,%5,%6,%7}, {%8,%9}, {%0,%1,%2,%3};"
        : "+f"(c[0]), "+f"(c[1]), "+f"(c[2]), "+f"(c[3])
        : "r"(a[0]), "r"(a[1]), "r"(a[2]), "r"(a[3]), "r"(b[0]), "r"(b[1]));
}
__device__ __forceinline__ uint32_t pack2(float v0, float v1, float& l0, float& l1) {
    __nv_bfloat16 h0 = __float2bfloat16(v0), h1 = __float2bfloat16(v1);
    l0 = v0 - __bfloat162float(h0);
    l1 = v1 - __bfloat162float(h1);
    return (uint32_t)__bfloat16_as_ushort(h0) | ((uint32_t)__bfloat16_as_ushort(h1) << 16);
}
__device__ __forceinline__ uint32_t pack2b(float l0, float l1) {
    return (uint32_t)__bfloat16_as_ushort(__float2bfloat16(l0)) |
           ((uint32_t)__bfloat16_as_ushort(__float2bfloat16(l1)) << 16);
}

// ---------------- weight prep: [N,K] f32 -> [N,3K] bf16 = [Wh|Wh|Wl] ----------
__global__ void prep_w(const float* __restrict__ src, __nv_bfloat16* __restrict__ dst,
                       int N, int K)
{
    int i = blockIdx.x * 256 + threadIdx.x;
    if (i >= N * K) return;
    int n = i / K, k = i % K;
    float v = src[i];
    __nv_bfloat16 h = __float2bfloat16(v);
    float l = v - __bfloat162float(h);
    size_t base = (size_t)n * 3 * K;
    dst[base + k]         = h;
    dst[base + K + k]     = h;
    dst[base + 2 * K + k] = __float2bfloat16(l);
}

// ======================= warp-MMA bf16 GEMM ===================================
// D[128 tok, 64 nch] per CTA = sum over packed 3K of A_split * Wpacked
// A token-major [tok][2K] = [hi|lo]; W [nch][3K] = [Wh|Wh|Wl]
// seg 0: Ahi*Wh, seg 1: Alo*Wh, seg 2: Ahi*Wl  (error-compensated product)
// EPI 0: f32 channel-major outF[b][outC][HW]
// EPI 1: +bias, gelu -> split bf16 token-major outS (row nRowW, lo at +nLo)
// EPI 2: +bias, gelu -> f32 channel-major
// EPI 3: +res (channel-major f32) -> f32 channel-major
template<int K, int EPI>
__global__ __launch_bounds__(256) void mma_gemm(
    const __nv_bfloat16* __restrict__ Ag_, const __nv_bfloat16* __restrict__ Wp,
    const float* __restrict__ bias, const float* __restrict__ res,
    float* __restrict__ outF, __nv_bfloat16* __restrict__ outS,
    int outC, int nRowW, int nLo)
{
    constexpr int SEGC = K / 32, NCH = 3 * SEGC;
    constexpr int AST = 40;                       // smem stride in bf16 units
    __shared__ __align__(16) char sm[33280];      // A/B buffers union Cs
    __nv_bfloat16* Abuf[2] = { (__nv_bfloat16*)sm,
                               (__nv_bfloat16*)sm + 128 * AST };
    __nv_bfloat16* Bbuf[2] = { (__nv_bfloat16*)sm + 2 * 128 * AST,
                               (__nv_bfloat16*)sm + 2 * 128 * AST + 64 * AST };
    float (*Cs)[65] = (float(*)[65])sm;

    const int tid = threadIdx.x;
    const int wid = tid >> 5, lane = tid & 31;
    const int g = lane >> 2, t2 = (lane & 3) * 2;
    const int wm = wid & 3, wn = wid >> 2;        // warp grid: 4 (M) x 2 (N)
    const size_t tok0 = (size_t)blockIdx.x * 128;
    const int n0 = blockIdx.y * 64;
    const char* Agc = (const char*)(Ag_ + tok0 * (2 * K));
    const char* Bgc = (const char*)(Wp + (size_t)n0 * (3 * K));

    float acc[2][4][4];
    #pragma unroll
    for (int mi = 0; mi < 2; mi++)
        #pragma unroll
        for (int ni = 0; ni < 4; ni++)
            #pragma unroll
            for (int q = 0; q < 4; q++) acc[mi][ni][q] = 0.f;

    auto issue = [&](int kc, int buf) {
        int seg = kc / SEGC, wi = kc % SEGC;
        int acol = ((seg == 1) ? K : 0) + wi * 32;   // seg2 reuses hi
        const char* As = Agc + acol * 2;
        const char* Bs = Bgc + kc * 64;
        #pragma unroll
        for (int i = 0; i < 2; i++) {                // A: 128 rows x 4 x 16B
            int v = tid + i * 256;
            int r = v >> 2, j = v & 3;
            cpa16(smem_u32(Abuf[buf] + r * AST + j * 8),
                  As + (size_t)r * (4 * K) + j * 16);
        }
        {                                            // B: 64 rows x 4 x 16B
            int r = tid >> 2, j = tid & 3;
            cpa16(smem_u32(Bbuf[buf] + r * AST + j * 8),
                  Bs + (size_t)r * (6 * K) + j * 16);
        }
        asm volatile("cp.async.commit_group;" ::: "memory");
    };

    auto compute = [&](int buf) {
        const __nv_bfloat16* Ab = Abuf[buf];
        const __nv_bfloat16* Bb = Bbuf[buf];
        #pragma unroll
        for (int ks = 0; ks < 2; ks++) {
            uint32_t af[2][4], bfr[4][2];
            int c = ks * 16 + t2;
            #pragma unroll
            for (int mi = 0; mi < 2; mi++) {
                int r = wm * 32 + mi * 16 + g;
                af[mi][0] = lds32(Ab + r * AST + c);
                af[mi][1] = lds32(Ab + (r + 8) * AST + c);
                af[mi][2] = lds32(Ab + r * AST + c + 8);
                af[mi][3] = lds32(Ab + (r + 8) * AST + c + 8);
            }
            #pragma unroll
            for (int ni = 0; ni < 4; ni++) {
                int nr = wn * 32 + ni * 8 + g;
                bfr[ni][0] = lds32(Bb + nr * AST + c);
                bfr[ni][1] = lds32(Bb + nr * AST + c + 8);
            }
            #pragma unroll
            for (int mi = 0; mi < 2; mi++)
                #pragma unroll
                for (int ni = 0; ni < 4; ni++)
                    mma16816(acc[mi][ni], af[mi], bfr[ni]);
        }
    };

    issue(0, 0);
    for (int i = 0; i < NCH; i++) {
        int cb = i & 1;
        if (i + 1 < NCH) {
            issue(i + 1, cb ^ 1);
            asm volatile("cp.async.wait_group 1;" ::: "memory");
        } else {
            asm volatile("cp.async.wait_group 0;" ::: "memory");
        }
        __syncthreads();
        compute(cb);
        __syncthreads();
    }

    // -------- stage accumulators to smem (coalesced stores afterwards) -------
    #pragma unroll
    for (int mi = 0; mi < 2; mi++)
        #pragma unroll
        for (int ni = 0; ni < 4; ni++) {
            int m = wm * 32 + mi * 16 + g;
            int n = wn * 32 + ni * 8 + t2;
            Cs[m][n]         = acc[mi][ni][0];
            Cs[m][n + 1]     = acc[mi][ni][1];
            Cs[m + 8][n]     = acc[mi][ni][2];
            Cs[m + 8][n + 1] = acc[mi][ni][3];
        }
    __syncthreads();

    if (EPI == 1) {
        int tok_l = tid >> 1, half = (tid & 1) * 32;
        size_t tok = tok0 + tok_l;
        uint32_t hp[16], lp[16];
        #pragma unroll
        for (int j = 0; j < 16; j++) {
            int ch = half + 2 * j;
            float v0 = gelu_exact(Cs[tok_l][ch]     + __ldg(&bias[n0 + ch]));
            float v1 = gelu_exact(Cs[tok_l][ch + 1] + __ldg(&bias[n0 + ch + 1]));
            float l0, l1;
            hp[j] = pack2(v0, v1, l0, l1);
            lp[j] = pack2b(l0, l1);
        }
        uint4* dh = (uint4*)(outS + tok * nRowW + n0 + half);
        uint4* dl = (uint4*)(outS + tok * nRowW + nLo + n0 + half);
        #pragma unroll
        for (int q = 0; q < 4; q++) { dh[q] = ((uint4*)hp)[q]; dl[q] = ((uint4*)lp)[q]; }
    } else {
        const int bq = (int)(tok0 >> 14);
        const int tl0 = (int)(tok0 & 16383);
        #pragma unroll 4
        for (int i = tid; i < 64 * 128; i += 256) {
            int ch = i >> 7, tl_ = i & 127;
            float v = Cs[tl_][ch];
            int chg = n0 + ch;
            if (EPI == 2) v = gelu_exact(v + __ldg(&bias[chg]));
            if (EPI == 3) v += res[((size_t)bq * CC + chg) * HWH + tl0 + tl_];
            outF[((size_t)bq * outC + chg) * HWH + tl0 + tl_] = v;
        }
    }
}

// ---------------- LayerNorm -> f32 (opt) + split bf16 token-major -------------
template<bool F32OUT>
__global__ __launch_bounds__(256) void ln_split(
    const float* __restrict__ x, const float* __restrict__ g,
    const float* __restrict__ bta, float* __restrict__ outF,
    __nv_bfloat16* __restrict__ outS)
{
    __shared__ float t[CC][33];
    __shared__ float s_mean[32], s_inv[32];
    const int b = blockIdx.y, p0 = blockIdx.x * 32;
    const int tid = threadIdx.x, w = tid >> 5, l = tid & 31;
    const float* xb = x + (size_t)b * CC * HWH + p0;
    for (int i = tid; i < CC * 32; i += 256) {
        int c = i >> 5, tk = i & 31;
        t[c][tk] = xb[(size_t)c * HWH + tk];
    }
    __syncthreads();
    #pragma unroll
    for (int r = 0; r < 4; r++) {
        int tk = w * 4 + r;
        float s = 0.f, ss = 0.f;
        #pragma unroll
        for (int c = l; c < CC; c += 32) { float v = t[c][tk]; s += v; ss += v * v; }
        #pragma unroll
        for (int o = 16; o; o >>= 1) {
            s  += __shfl_xor_sync(0xFFFFFFFFu, s, o);
            ss += __shfl_xor_sync(0xFFFFFFFFu, ss, o);
        }
        if (l == 0) {
            float m = s * (1.0f / CC);
            s_mean[tk] = m;
            s_inv[tk]  = rsqrtf(ss * (1.0f / CC) - m * m + 1e-5f);
        }
    }
    __syncthreads();
    if (F32OUT) {
        float* ob = outF + (size_t)b * CC * HWH + p0;
        for (int i = tid; i < CC * 32; i += 256) {
            int c = i >> 5, tk = i & 31;
            ob[(size_t)c * HWH + tk] =
                (t[c][tk] - s_mean[tk]) * s_inv[tk] * __ldg(&g[c]) + __ldg(&bta[c]);
        }
    }
    #pragma unroll
    for (int r = 0; r < 4; r++) {
        int tk = w * 4 + r;
        if (l < 24) {
            size_t tok = (size_t)b * HWH + p0 + tk;
            float m = s_mean[tk], inv = s_inv[tk];
            uint32_t hp[4], lp[4];
            #pragma unroll
            for (int j = 0; j < 4; j++) {
                int c = l * 8 + 2 * j;
                float v0 = (t[c][tk]     - m) * inv * __ldg(&g[c])     + __ldg(&bta[c]);
                float v1 = (t[c + 1][tk] - m) * inv * __ldg(&g[c + 1]) + __ldg(&bta[c + 1]);
                float l0, l1;
                hp[j] = pack2(v0, v1, l0, l1);
                lp[j] = pack2b(l0, l1);
            }
            *(uint4*)(outS + tok * 384 + l * 8)       = *(uint4*)hp;
            *(uint4*)(outS + tok * 384 + 192 + l * 8) = *(uint4*)lp;
        }
    }
}

// ---------------- depthwise 3x3, pad 1 ---------------------------------------
__global__ __launch_bounds__(256) void dwconv_kernel(
    const float* __restrict__ in, const float* __restrict__ w,
    float* __restrict__ out)
{
    int p  = blockIdx.x * 256 + threadIdx.x;
    int bc = blockIdx.y;
    int c  = bc % C3;
    int y  = p >> 7, x0 = p & 127;
    const float* ip = in + (size_t)bc * HWH;
    const float* wp = w + c * 9;
    float acc = 0.f;
    #pragma unroll
    for (int ky = 0; ky < 3; ky++) {
        int yy = y + ky - 1;
        if (yy < 0 || yy >= HH) continue;
        #pragma unroll
        for (int kx = 0; kx < 3; kx++) {
            int xx = x0 + kx - 1;
            if (xx < 0 || xx >= WW) continue;
            acc += wp[ky * 3 + kx] * ip[yy * WW + xx];
        }
    }
    out[(size_t)bc * HWH + p] = acc;
}

// ---------------- q,k inverse L2 norms ---------------------------------------
__global__ __launch_bounds__(256) void rownorm_kernel(
    const float* __restrict__ qkv, float* __restrict__ invn)
{
    int b = blockIdx.x / 384;
    int c = blockIdx.x % 384;
    const float* row = qkv + ((size_t)b * C3 + c) * HWH;
    float ss = 0.f;
    for (int i = threadIdx.x; i < HWH; i += 256) { float v = row[i]; ss += v * v; }
    __shared__ float red[256];
    red[threadIdx.x] = ss;
    __syncthreads();
    for (int s = 128; s > 0; s >>= 1) {
        if (threadIdx.x < s) red[threadIdx.x] += red[threadIdx.x + s];
        __syncthreads();
    }
    if (threadIdx.x == 0)
        invn[blockIdx.x] = 1.0f / fmaxf(sqrtf(red[0]), 1e-12f);
}

// ---------------- attn partial = q k^T over split-n ---------------------------
__global__ __launch_bounds__(256) void qk_kernel(
    const float* __restrict__ qkv, const float* __restrict__ invn,
    const float* __restrict__ temp, float* __restrict__ part)
{
    int bh = blockIdx.x;
    int b = bh / HEADS, hd = bh % HEADS;
    const float* q = qkv + ((size_t)b * C3 + hd * CP) * HWH;
    const float* k = qkv + ((size_t)b * C3 + CC + hd * CP) * HWH;
    __shared__ float Qs[32][65];
    __shared__ float Ks[32][65];
    const int n0 = blockIdx.y * (HWH / NSPLIT);
    float acc[4] = {0.f, 0.f, 0.f, 0.f};
    const int c = threadIdx.x & 31;
    const int dbase = (threadIdx.x >> 5) * 4;
    for (int t = 0; t < HWH / NSPLIT; t += 64) {
        for (int i = threadIdx.x; i < 32 * 64; i += 256) {
            int r = i >> 6, col = i & 63;
            Qs[r][col] = q[(size_t)r * HWH + n0 + t + col];
            Ks[r][col] = k[(size_t)r * HWH + n0 + t + col];
        }
        __syncthreads();
        #pragma unroll 8
        for (int n = 0; n < 64; n++) {
            float qv = Qs[c][n];
            acc[0] = fmaf(qv, Ks[dbase + 0][n], acc[0]);
            acc[1] = fmaf(qv, Ks[dbase + 1][n], acc[1]);
            acc[2] = fmaf(qv, Ks[dbase + 2][n], acc[2]);
            acc[3] = fmaf(qv, Ks[dbase + 3][n], acc[3]);
        }
        __syncthreads();
    }
    float iq = invn[b * 384 + hd * CP + c];
    float tp = temp[hd];
    #pragma unroll
    for (int j = 0; j < 4; j++) {
        int d = dbase + j;
        float ik = invn[b * 384 + CC + hd * CP + d];
        part[((size_t)blockIdx.y * (BB * HEADS) + bh) * 1024 + c * 32 + d]
            = acc[j] * iq * ik * tp;
    }
}

// ---------------- reduce + 3x3 head conv + softmax ----------------------------
__global__ __launch_bounds__(256) void headconv_softmax_kernel(
    const float* __restrict__ part, const float* __restrict__ w_head,
    float* __restrict__ attnF)
{
    int b = blockIdx.x;
    __shared__ float A[HEADS * 1024];
    __shared__ float wsh[HEADS * HEADS * 9];
    int tid = threadIdx.x;
    if (tid < HEADS * HEADS * 9) wsh[tid] = w_head[tid];
    for (int i = tid; i < HEADS * 1024; i += 256) {
        int hd = i >> 10, rest = i & 1023;
        float s = 0.f;
        #pragma unroll
        for (int sp = 0; sp < NSPLIT; sp++)
            s += part[((size_t)sp * (BB * HEADS) + b * HEADS + hd) * 1024 + rest];
        A[i] = s;
    }
    __syncthreads();
    float cv[24];
    #pragma unroll
    for (int r = 0; r < 24; r++) {
        int i  = tid * 24 + r;
        int ho = i >> 10;
        int yx = i & 1023;
        int y = yx >> 5, x = yx & 31;
        float s = 0.f;
        for (int hi = 0; hi < HEADS; hi++) {
            const float* Ah = &A[hi * 1024];
            #pragma unroll
            for (int ky = 0; ky < 3; ky++) {
                int yy = y + ky - 1;
                if (yy < 0 || yy > 31) continue;
                #pragma unroll
                for (int kx = 0; kx < 3; kx++) {
                    int xx = x + kx - 1;
                    if (xx < 0 || xx > 31) continue;
                    s += wsh[((ho * HEADS + hi) * 3 + ky) * 3 + kx] * Ah[yy * 32 + xx];
                }
            }
        }
        cv[r] = s;
    }
    __syncthreads();
    #pragma unroll
    for (int r = 0; r < 24; r++) A[tid * 24 + r] = cv[r];
    __syncthreads();
    if (tid < HEADS * 32) {
        float* row = &A[tid * 32];
        float mx = -1e30f;
        for (int j = 0; j < 32; j++) mx = fmaxf(mx, row[j]);
        float sum = 0.f, e[32];
        for (int j = 0; j < 32; j++) { e[j] = expf(row[j] - mx); sum += e[j]; }
        float inv = 1.0f / sum;
        float* o = attnF + (size_t)b * (HEADS * 1024) + tid * 32;
        for (int j = 0; j < 32; j++) o[j] = e[j] * inv;
    }
}

// ---------------- out = attn @ v -> split bf16 token-major --------------------
__global__ __launch_bounds__(256) void av_kernel(
    const float* __restrict__ attn, const float* __restrict__ qkv,
    __nv_bfloat16* __restrict__ avs)
{
    int bh = blockIdx.y;
    int b = bh / HEADS, hd = bh % HEADS;
    __shared__ float As[32][32];
    for (int i = threadIdx.x; i < 1024; i += 256)
        ((float*)As)[i] = attn[(size_t)bh * 1024 + i];
    __syncthreads();
    int n = blockIdx.x * 256 + threadIdx.x;
    const float* v = qkv + ((size_t)b * C3 + 2 * CC + hd * CP) * HWH + n;
    float vv[32];
    #pragma unroll
    for (int d = 0; d < 32; d++) vv[d] = v[(size_t)d * HWH];
    uint32_t hp[16], lp[16];
    #pragma unroll
    for (int c2 = 0; c2 < 16; c2++) {
        float s0 = 0.f, s1 = 0.f;
        #pragma unroll
        for (int d = 0; d < 32; d++) {
            s0 = fmaf(As[2 * c2][d], vv[d], s0);
            s1 = fmaf(As[2 * c2 + 1][d], vv[d], s1);
        }
        float l0, l1;
        hp[c2] = pack2(s0, s1, l0, l1);
        lp[c2] = pack2b(l0, l1);
    }
    size_t tok = (size_t)b * HWH + n;
    uint4* dh = (uint4*)(avs + tok * 384 + hd * 32);
    uint4* dl = (uint4*)(avs + tok * 384 + 192 + hd * 32);
    #pragma unroll
    for (int q = 0; q < 4; q++) { dh[q] = ((uint4*)hp)[q]; dl[q] = ((uint4*)lp)[q]; }
}

// ---------------- spatial gate ------------------------------------------------
__global__ __launch_bounds__(256) void gate_kernel(
    const float* __restrict__ y4, const float* __restrict__ w_sa,
    const float* __restrict__ b_sa, float* __restrict__ gate)
{
    __shared__ float tile[18][18];
    __shared__ float ws[CC * 9];
    int bx = blockIdx.x & 7;
    int by = (blockIdx.x >> 3) & 7;
    int b  = blockIdx.x >> 6;
    int tx = threadIdx.x & 15, ty = threadIdx.x >> 4;
    for (int i = threadIdx.x; i < CC * 9; i += 256) ws[i] = w_sa[i];
    float acc = 0.f;
    for (int c = 0; c < CC; c++) {
        const float* ip = y4 + ((size_t)b * CC + c) * HWH;
        for (int i = threadIdx.x; i < 18 * 18; i += 256) {
            int ly = i / 18, lx = i % 18;
            int gy = by * 16 + ly - 1, gx = bx * 16 + lx - 1;
            tile[ly][lx] = (gy >= 0 && gy < HH && gx >= 0 && gx < WW)
                               ? ip[gy * WW + gx] : 0.f;
        }
        __syncthreads();
        const float* wp = &ws[c * 9];
        #pragma unroll
        for (int ky = 0; ky < 3; ky++)
            #pragma unroll
            for (int kx = 0; kx < 3; kx++)
                acc = fmaf(wp[ky * 3 + kx], tile[ty + ky][tx + kx], acc);
        __syncthreads();
    }
    int oy = by * 16 + ty, ox = bx * 16 + tx;
    gate[(size_t)b * HWH + oy * WW + ox] =
        1.0f / (1.0f + expf(-(acc + b_sa[0])));
}

// ---------------- final: out = x2 + y4 * gate ---------------------------------
__global__ __launch_bounds__(256) void final_kernel(
    const float* __restrict__ x2, const float* __restrict__ y4,
    const float* __restrict__ gate, float* __restrict__ out)
{
    int i4 = blockIdx.x * 256 + threadIdx.x;
    int elem = i4 * 4;
    int b = elem / (CC * HWH);
    int p = elem % HWH;
    float4 a = ((const float4*)x2)[i4];
    float4 y = ((const float4*)y4)[i4];
    float4 g = ((const float4*)gate)[(size_t)b * (HWH / 4) + (p >> 2)];
    float4 r;
    r.x = a.x + y.x * g.x;
    r.y = a.y + y.y * g.y;
    r.z = a.z + y.z * g.z;
    r.w = a.w + y.w * g.w;
    ((float4*)out)[i4] = r;
}

// =============================================================================
extern "C" void kernel_launch(void* const* d_in, const int* in_sizes, int n_in,
                              void* d_out, int out_size)
{
    const float* x      = (const float*)d_in[0];
    const float* g1     = (const float*)d_in[1];
    const float* b1     = (const float*)d_in[2];
    const float* w_qkv  = (const float*)d_in[3];
    const float* w_dw   = (const float*)d_in[4];
    const float* temp   = (const float*)d_in[5];
    const float* w_head = (const float*)d_in[6];
    const float* w_proj = (const float*)d_in[7];
    const float* g2     = (const float*)d_in[8];
    const float* b2     = (const float*)d_in[9];
    const float* w_fc1  = (const float*)d_in[10];
    const float* b_fc1  = (const float*)d_in[11];
    const float* w_fc2  = (const float*)d_in[12];
    const float* b_fc2  = (const float*)d_in[13];
    const float* w_sa   = (const float*)d_in[14];
    const float* b_sa   = (const float*)d_in[15];
    float* out = (float*)d_out;

    float *p_x1, *p_qkv1, *p_qkv2, *p_invn, *p_part, *p_attn, *p_x2, *p_y4, *p_gate;
    __nv_bfloat16 *p_x1s, *p_avs, *p_xns, *p_h1s, *p_wq, *p_wp, *p_w1, *p_w2;
    cudaGetSymbolAddress((void**)&p_x1,   g_x1);
    cudaGetSymbolAddress((void**)&p_x1s,  g_x1s);
    cudaGetSymbolAddress((void**)&p_qkv1, g_qkv1);
    cudaGetSymbolAddress((void**)&p_qkv2, g_qkv2);
    cudaGetSymbolAddress((void**)&p_invn, g_invn);
    cudaGetSymbolAddress((void**)&p_part, g_part);
    cudaGetSymbolAddress((void**)&p_attn, g_attn);
    cudaGetSymbolAddress((void**)&p_avs,  g_avs);
    cudaGetSymbolAddress((void**)&p_x2,   g_x2);
    cudaGetSymbolAddress((void**)&p_xns,  g_xns);
    cudaGetSymbolAddress((void**)&p_h1s,  g_h1s);
    cudaGetSymbolAddress((void**)&p_y4,   g_y4);
    cudaGetSymbolAddress((void**)&p_gate, g_gate);
    cudaGetSymbolAddress((void**)&p_wq,   g_wq);
    cudaGetSymbolAddress((void**)&p_wp,   g_wp);
    cudaGetSymbolAddress((void**)&p_w1,   g_w1);
    cudaGetSymbolAddress((void**)&p_w2,   g_w2);

    // weight prep (tiny)
    prep_w<<<(C3 * CC + 255) / 256, 256>>>(w_qkv, p_wq, C3, CC);
    prep_w<<<(CC * CC + 255) / 256, 256>>>(w_proj, p_wp, CC, CC);
    prep_w<<<(HID * CC + 255) / 256, 256>>>(w_fc1, p_w1, HID, CC);
    prep_w<<<(CC * HID + 255) / 256, 256>>>(w_fc2, p_w2, CC, HID);

    // 1) LN1: x -> x1 (f32 channel-major) + x1s (split bf16 token-major)
    ln_split<true><<<dim3(HWH / 32, BB), 256>>>(x, g1, b1, p_x1, p_x1s);

    // 2) qkv GEMM: 576 out-ch = 9 N-tiles of 64
    mma_gemm<192, 0><<<dim3(NTOK / 128, 9), 256>>>(
        p_x1s, p_wq, nullptr, nullptr, p_qkv1, nullptr, C3, 0, 0);

    // 3) depthwise 3x3
    dwconv_kernel<<<dim3(HWH / 256, BB * C3), 256>>>(p_qkv1, w_dw, p_qkv2);

    // 4-7) attention path
    rownorm_kernel<<<BB * 2 * CC, 256>>>(p_qkv2, p_invn);
    qk_kernel<<<dim3(BB * HEADS, NSPLIT), 256>>>(p_qkv2, p_invn, temp, p_part);
    headconv_softmax_kernel<<<BB, 256>>>(p_part, w_head, p_attn);
    av_kernel<<<dim3(HWH / 256, BB * HEADS), 256>>>(p_attn, p_qkv2, p_avs);

    // 8) proj GEMM + residual x1 -> x2
    mma_gemm<192, 3><<<dim3(NTOK / 128, 3), 256>>>(
        p_avs, p_wp, nullptr, p_x1, p_x2, nullptr, CC, 0, 0);

    // 9) LN2: x2 -> xns (split only)
    ln_split<false><<<dim3(HWH / 32, BB), 256>>>(p_x2, g2, b2, nullptr, p_xns);

    // 10) fc1 GEMM + bias + gelu -> h1s (384 out = 6 N-tiles)
    mma_gemm<192, 1><<<dim3(NTOK / 128, 6), 256>>>(
        p_xns, p_w1, b_fc1, nullptr, nullptr, p_h1s, 0, 2 * HID, HID);

    // 11) fc2 GEMM (K=384) + bias + gelu -> y4
    mma_gemm<384, 2><<<dim3(NTOK / 128, 3), 256>>>(
        p_h1s, p_w2, b_fc2, nullptr, p_y4, nullptr, CC, 0, 0);

    // 12) gate, 13) final
    gate_kernel<<<BB * 64, 256>>>(p_y4, w_sa, b_sa, p_gate);
    final_kernel<<<(BB * CC * HWH / 4) / 256, 256>>>(p_x2, p_y4, p_gate, out);

    (void)in_sizes; (void)n_in; (void)out_size;
}

// round 6
// speedup vs baseline: 1.2091x; 1.0742x over previous
#include <cuda_runtime.h>
#include <cuda_bf16.h>
#include <math.h>
#include <stdint.h>

#define BB 4
#define CC 192
#define HH 128
#define WW 128
#define HWH (HH*WW)          // 16384
#define C3 576
#define HID 384
#define HEADS 6
#define CP 32
#define NSPLIT 8
#define NTOK (BB*HWH)        // 65536

// ---------------- scratch (device globals; allocation-free) -------------------
__device__ float         g_x1  [(size_t)BB*CC*HWH];
__device__ __nv_bfloat16 g_x1s [(size_t)NTOK*2*CC];
__device__ float         g_qkv1[(size_t)BB*C3*HWH];
__device__ float         g_qkv2[(size_t)BB*C3*HWH];
__device__ float         g_invn[BB*2*CC];
__device__ float         g_part[NSPLIT*BB*HEADS*CP*CP];
__device__ float         g_attn[BB*HEADS*CP*CP];
__device__ __nv_bfloat16 g_avs [(size_t)NTOK*2*CC];
__device__ float         g_x2  [(size_t)BB*CC*HWH];
__device__ __nv_bfloat16 g_xns [(size_t)NTOK*2*CC];
__device__ __nv_bfloat16 g_h1s [(size_t)NTOK*2*HID];
__device__ float         g_y4  [(size_t)BB*CC*HWH];
__device__ float         g_gate[NTOK];
__device__ __nv_bfloat16 g_wq  [(size_t)C3 *3*CC];
__device__ __nv_bfloat16 g_wp  [(size_t)CC *3*CC];
__device__ __nv_bfloat16 g_w1  [(size_t)HID*3*CC];
__device__ __nv_bfloat16 g_w2  [(size_t)CC *3*HID];

// ---------------- small helpers ----------------------------------------------
__device__ __forceinline__ float gelu_exact(float x) {
    return 0.5f * x * (1.0f + erff(x * 0.70710678118654752f));
}
__device__ __forceinline__ uint32_t smem_u32(const void* p) {
    uint32_t a;
    asm("{ .reg .u64 t; cvta.to.shared.u64 t, %1; cvt.u32.u64 %0, t; }"
        : "=r"(a) : "l"(p));
    return a;
}
__device__ __forceinline__ void cpa16(uint32_t dst, const void* src) {
    asm volatile("cp.async.cg.shared.global [%0], [%1], 16;" :: "r"(dst), "l"(src) : "memory");
}
__device__ __forceinline__ void mma16816(float* c, const uint32_t* a, const uint32_t* b) {
    asm volatile(
        "mma.sync.aligned.m16n8k16.row.col.f32.bf16.bf16.f32 "
        "{%0,%1,%2,%3}, {%4,%5,%6,%7}, {%8,%9}, {%0,%1,%2,%3};"
        : "+f"(c[0]), "+f"(c[1]), "+f"(c[2]), "+f"(c[3])
        : "r"(a[0]), "r"(a[1]), "r"(a[2]), "r"(a[3]), "r"(b[0]), "r"(b[1]));
}
#define LDMX4(r, addr)                                                          \
    asm volatile("ldmatrix.sync.aligned.m8n8.x4.shared.b16 {%0,%1,%2,%3}, [%4];" \
        : "=r"((r)[0]), "=r"((r)[1]), "=r"((r)[2]), "=r"((r)[3]) : "r"(addr))
__device__ __forceinline__ uint32_t pack2(float v0, float v1, float& l0, float& l1) {
    __nv_bfloat16 h0 = __float2bfloat16(v0), h1 = __float2bfloat16(v1);
    l0 = v0 - __bfloat162float(h0);
    l1 = v1 - __bfloat162float(h1);
    return (uint32_t)__bfloat16_as_ushort(h0) | ((uint32_t)__bfloat16_as_ushort(h1) << 16);
}
__device__ __forceinline__ uint32_t pack2b(float l0, float l1) {
    return (uint32_t)__bfloat16_as_ushort(__float2bfloat16(l0)) |
           ((uint32_t)__bfloat16_as_ushort(__float2bfloat16(l1)) << 16);
}

// ---------------- weight prep: [N,K] f32 -> [N,3K] bf16 = [Wh|Wh|Wl] ----------
__global__ void prep_w(const float* __restrict__ src, __nv_bfloat16* __restrict__ dst,
                       int N, int K)
{
    int i = blockIdx.x * 256 + threadIdx.x;
    if (i >= N * K) return;
    int n = i / K, k = i % K;
    float v = src[i];
    __nv_bfloat16 h = __float2bfloat16(v);
    float l = v - __bfloat162float(h);
    size_t base = (size_t)n * 3 * K;
    dst[base + k]         = h;
    dst[base + K + k]     = h;
    dst[base + 2 * K + k] = __float2bfloat16(l);
}

// ======================= warp-MMA bf16 GEMM (128 x 192 tile) ==================
// D[128 tok, 192 nch] per CTA; A token-major [tok][2K]=[hi|lo]; W [nch][3K]=[Wh|Wh|Wl]
// seg 0: Ahi*Wh, seg 1: Alo*Wh, seg 2: Ahi*Wl
// EPI 0: f32 channel-major   EPI 1: +bias,gelu -> split bf16 token-major
// EPI 2: +bias,gelu -> f32 channel-major   EPI 3: +res -> f32 channel-major
// Dynamic smem: 51200 B = A bufs 2x10240 + B bufs 2x15360 (stride AST=40 bf16
// = 80 B, 16B-aligned for cp.async/ldmatrix, conflict-free groups 5r mod 8).
template<int K, int EPI>
__global__ __launch_bounds__(256) void mma_gemm(
    const __nv_bfloat16* __restrict__ Ag_, const __nv_bfloat16* __restrict__ Wp,
    const float* __restrict__ bias, const float* __restrict__ res,
    float* __restrict__ outF, __nv_bfloat16* __restrict__ outS,
    int outC, int nRowW, int nLo)
{
    constexpr int SEGC = K / 32, NCH = 3 * SEGC;
    constexpr int AST = 40;                       // smem stride in bf16 units
    extern __shared__ __align__(16) char sm[];
    const uint32_t smb = smem_u32(sm);
    const uint32_t sA[2] = { smb, smb + 10240 };
    const uint32_t sB[2] = { smb + 20480, smb + 35840 };
    float (*Cs)[50] = (float(*)[50])sm;           // 128 x 50 floats = 25600 B

    const int tid = threadIdx.x;
    const int wid = tid >> 5, lane = tid & 31;
    const int g = lane >> 2, t2 = (lane & 3) * 2;
    const int wm = wid & 1, wn = wid >> 1;        // warp grid: 2 (M) x 4 (N)
    const size_t tok0 = (size_t)blockIdx.x * 128;
    const int n0 = blockIdx.y * 192;
    const char* Agc = (const char*)(Ag_ + tok0 * (2 * K));
    const char* Bgc = (const char*)(Wp + (size_t)n0 * (3 * K));

    // ldmatrix lane-address components (byte offsets within a buffer)
    const uint32_t a_lrow = (uint32_t)(wm * 64 + (lane & 15)) * (AST * 2) + ((lane >> 4) << 4);
    const uint32_t b_lrow = (uint32_t)(wn * 48 + (lane & 7) + ((lane >> 4) << 3)) * (AST * 2)
                          + (((lane >> 3) & 1) << 4);

    float acc[4][6][4];
    #pragma unroll
    for (int mi = 0; mi < 4; mi++)
        #pragma unroll
        for (int ni = 0; ni < 6; ni++)
            #pragma unroll
            for (int q = 0; q < 4; q++) acc[mi][ni][q] = 0.f;

    auto issue = [&](int kc, int buf) {
        int seg = kc / SEGC, wi = kc % SEGC;
        int acol = ((seg == 1) ? K : 0) + wi * 32;   // seg 2 reuses hi
        const char* As = Agc + acol * 2;
        const char* Bs = Bgc + kc * 64;
        #pragma unroll
        for (int i = 0; i < 2; i++) {                // A: 128 rows x 4 x 16B
            int v = tid + i * 256;
            int r = v >> 2, j = v & 3;
            cpa16(sA[buf] + r * (AST * 2) + j * 16, As + (size_t)r * (4 * K) + j * 16);
        }
        #pragma unroll
        for (int i = 0; i < 3; i++) {                // B: 192 rows x 4 x 16B
            int v = tid + i * 256;
            int r = v >> 2, j = v & 3;
            cpa16(sB[buf] + r * (AST * 2) + j * 16, Bs + (size_t)r * (6 * K) + j * 16);
        }
        asm volatile("cp.async.commit_group;" ::: "memory");
    };

    issue(0, 0);
    for (int i = 0; i < NCH; i++) {
        int cb = i & 1;
        if (i + 1 < NCH) {
            issue(i + 1, cb ^ 1);
            asm volatile("cp.async.wait_group 1;" ::: "memory");
        } else {
            asm volatile("cp.async.wait_group 0;" ::: "memory");
        }
        __syncthreads();
        // compute chunk (K=32 -> 2 ksteps of 16)
        #pragma unroll
        for (int ks = 0; ks < 2; ks++) {
            uint32_t af[4][4], bfr[6][2];
            #pragma unroll
            for (int mi = 0; mi < 4; mi++) {
                uint32_t ad = sA[cb] + a_lrow + mi * 16 * (AST * 2) + ks * 32;
                LDMX4(af[mi], ad);
            }
            #pragma unroll
            for (int p = 0; p < 3; p++) {
                uint32_t r4[4];
                uint32_t bd = sB[cb] + b_lrow + p * 16 * (AST * 2) + ks * 32;
                LDMX4(r4, bd);
                bfr[2 * p][0] = r4[0]; bfr[2 * p][1] = r4[1];
                bfr[2 * p + 1][0] = r4[2]; bfr[2 * p + 1][1] = r4[3];
            }
            #pragma unroll
            for (int mi = 0; mi < 4; mi++)
                #pragma unroll
                for (int ni = 0; ni < 6; ni++)
                    mma16816(acc[mi][ni], af[mi], bfr[ni]);
        }
        __syncthreads();
    }

    // -------- epilogue: 4 slabs of 48 channels, staged through smem ----------
    const int bq = (int)(tok0 >> 14);
    const int tl0 = (int)(tok0 & 16383);
    for (int s = 0; s < 4; s++) {
        if (wn == s) {
            #pragma unroll
            for (int mi = 0; mi < 4; mi++)
                #pragma unroll
                for (int ni = 0; ni < 6; ni++) {
                    int m = wm * 64 + mi * 16 + g;
                    int n = ni * 8 + t2;
                    Cs[m][n]         = acc[mi][ni][0];
                    Cs[m][n + 1]     = acc[mi][ni][1];
                    Cs[m + 8][n]     = acc[mi][ni][2];
                    Cs[m + 8][n + 1] = acc[mi][ni][3];
                }
        }
        __syncthreads();
        const int chb = n0 + s * 48;
        if (EPI == 1) {
            int tokl = tid >> 1, co = (tid & 1) * 24;
            size_t tok = tok0 + tokl;
            uint32_t hp[12], lp[12];
            #pragma unroll
            for (int j = 0; j < 12; j++) {
                int ch = co + 2 * j;
                float v0 = gelu_exact(Cs[tokl][ch]     + __ldg(&bias[chb + ch]));
                float v1 = gelu_exact(Cs[tokl][ch + 1] + __ldg(&bias[chb + ch + 1]));
                float l0, l1;
                hp[j] = pack2(v0, v1, l0, l1);
                lp[j] = pack2b(l0, l1);
            }
            uint4* dh = (uint4*)(outS + tok * nRowW + chb + co);
            uint4* dl = (uint4*)(outS + tok * nRowW + nLo + chb + co);
            #pragma unroll
            for (int q = 0; q < 3; q++) { dh[q] = ((uint4*)hp)[q]; dl[q] = ((uint4*)lp)[q]; }
        } else {
            #pragma unroll 4
            for (int i = tid; i < 48 * 128; i += 256) {
                int ch = i >> 7, tl_ = i & 127;
                float v = Cs[tl_][ch];
                int chg = chb + ch;
                if (EPI == 2) v = gelu_exact(v + __ldg(&bias[chg]));
                if (EPI == 3) v += res[((size_t)bq * CC + chg) * HWH + tl0 + tl_];
                outF[((size_t)bq * outC + chg) * HWH + tl0 + tl_] = v;
            }
        }
        __syncthreads();
    }
}

// ---------------- LayerNorm -> f32 (opt) + split bf16 token-major -------------
template<bool F32OUT>
__global__ __launch_bounds__(256) void ln_split(
    const float* __restrict__ x, const float* __restrict__ g,
    const float* __restrict__ bta, float* __restrict__ outF,
    __nv_bfloat16* __restrict__ outS)
{
    __shared__ float t[CC][33];
    __shared__ float s_mean[32], s_inv[32];
    const int b = blockIdx.y, p0 = blockIdx.x * 32;
    const int tid = threadIdx.x, w = tid >> 5, l = tid & 31;
    const float* xb = x + (size_t)b * CC * HWH + p0;
    for (int i = tid; i < CC * 32; i += 256) {
        int c = i >> 5, tk = i & 31;
        t[c][tk] = xb[(size_t)c * HWH + tk];
    }
    __syncthreads();
    #pragma unroll
    for (int r = 0; r < 4; r++) {
        int tk = w * 4 + r;
        float s = 0.f, ss = 0.f;
        #pragma unroll
        for (int c = l; c < CC; c += 32) { float v = t[c][tk]; s += v; ss += v * v; }
        #pragma unroll
        for (int o = 16; o; o >>= 1) {
            s  += __shfl_xor_sync(0xFFFFFFFFu, s, o);
            ss += __shfl_xor_sync(0xFFFFFFFFu, ss, o);
        }
        if (l == 0) {
            float m = s * (1.0f / CC);
            s_mean[tk] = m;
            s_inv[tk]  = rsqrtf(ss * (1.0f / CC) - m * m + 1e-5f);
        }
    }
    __syncthreads();
    if (F32OUT) {
        float* ob = outF + (size_t)b * CC * HWH + p0;
        for (int i = tid; i < CC * 32; i += 256) {
            int c = i >> 5, tk = i & 31;
            ob[(size_t)c * HWH + tk] =
                (t[c][tk] - s_mean[tk]) * s_inv[tk] * __ldg(&g[c]) + __ldg(&bta[c]);
        }
    }
    #pragma unroll
    for (int r = 0; r < 4; r++) {
        int tk = w * 4 + r;
        if (l < 24) {
            size_t tok = (size_t)b * HWH + p0 + tk;
            float m = s_mean[tk], inv = s_inv[tk];
            uint32_t hp[4], lp[4];
            #pragma unroll
            for (int j = 0; j < 4; j++) {
                int c = l * 8 + 2 * j;
                float v0 = (t[c][tk]     - m) * inv * __ldg(&g[c])     + __ldg(&bta[c]);
                float v1 = (t[c + 1][tk] - m) * inv * __ldg(&g[c + 1]) + __ldg(&bta[c + 1]);
                float l0, l1;
                hp[j] = pack2(v0, v1, l0, l1);
                lp[j] = pack2b(l0, l1);
            }
            *(uint4*)(outS + tok * 384 + l * 8)       = *(uint4*)hp;
            *(uint4*)(outS + tok * 384 + 192 + l * 8) = *(uint4*)lp;
        }
    }
}

// ---------------- depthwise 3x3, pad 1 ---------------------------------------
__global__ __launch_bounds__(256) void dwconv_kernel(
    const float* __restrict__ in, const float* __restrict__ w,
    float* __restrict__ out)
{
    int p  = blockIdx.x * 256 + threadIdx.x;
    int bc = blockIdx.y;
    int c  = bc % C3;
    int y  = p >> 7, x0 = p & 127;
    const float* ip = in + (size_t)bc * HWH;
    const float* wp = w + c * 9;
    float acc = 0.f;
    #pragma unroll
    for (int ky = 0; ky < 3; ky++) {
        int yy = y + ky - 1;
        if (yy < 0 || yy >= HH) continue;
        #pragma unroll
        for (int kx = 0; kx < 3; kx++) {
            int xx = x0 + kx - 1;
            if (xx < 0 || xx >= WW) continue;
            acc += wp[ky * 3 + kx] * ip[yy * WW + xx];
        }
    }
    out[(size_t)bc * HWH + p] = acc;
}

// ---------------- q,k inverse L2 norms ---------------------------------------
__global__ __launch_bounds__(256) void rownorm_kernel(
    const float* __restrict__ qkv, float* __restrict__ invn)
{
    int b = blockIdx.x / 384;
    int c = blockIdx.x % 384;
    const float* row = qkv + ((size_t)b * C3 + c) * HWH;
    float ss = 0.f;
    for (int i = threadIdx.x; i < HWH; i += 256) { float v = row[i]; ss += v * v; }
    __shared__ float red[256];
    red[threadIdx.x] = ss;
    __syncthreads();
    for (int s = 128; s > 0; s >>= 1) {
        if (threadIdx.x < s) red[threadIdx.x] += red[threadIdx.x + s];
        __syncthreads();
    }
    if (threadIdx.x == 0)
        invn[blockIdx.x] = 1.0f / fmaxf(sqrtf(red[0]), 1e-12f);
}

// ---------------- attn partial = q k^T over split-n ---------------------------
__global__ __launch_bounds__(256) void qk_kernel(
    const float* __restrict__ qkv, const float* __restrict__ invn,
    const float* __restrict__ temp, float* __restrict__ part)
{
    int bh = blockIdx.x;
    int b = bh / HEADS, hd = bh % HEADS;
    const float* q = qkv + ((size_t)b * C3 + hd * CP) * HWH;
    const float* k = qkv + ((size_t)b * C3 + CC + hd * CP) * HWH;
    __shared__ float Qs[32][65];
    __shared__ float Ks[32][65];
    const int n0 = blockIdx.y * (HWH / NSPLIT);
    float acc[4] = {0.f, 0.f, 0.f, 0.f};
    const int c = threadIdx.x & 31;
    const int dbase = (threadIdx.x >> 5) * 4;
    for (int t = 0; t < HWH / NSPLIT; t += 64) {
        for (int i = threadIdx.x; i < 32 * 64; i += 256) {
            int r = i >> 6, col = i & 63;
            Qs[r][col] = q[(size_t)r * HWH + n0 + t + col];
            Ks[r][col] = k[(size_t)r * HWH + n0 + t + col];
        }
        __syncthreads();
        #pragma unroll 8
        for (int n = 0; n < 64; n++) {
            float qv = Qs[c][n];
            acc[0] = fmaf(qv, Ks[dbase + 0][n], acc[0]);
            acc[1] = fmaf(qv, Ks[dbase + 1][n], acc[1]);
            acc[2] = fmaf(qv, Ks[dbase + 2][n], acc[2]);
            acc[3] = fmaf(qv, Ks[dbase + 3][n], acc[3]);
        }
        __syncthreads();
    }
    float iq = invn[b * 384 + hd * CP + c];
    float tp = temp[hd];
    #pragma unroll
    for (int j = 0; j < 4; j++) {
        int d = dbase + j;
        float ik = invn[b * 384 + CC + hd * CP + d];
        part[((size_t)blockIdx.y * (BB * HEADS) + bh) * 1024 + c * 32 + d]
            = acc[j] * iq * ik * tp;
    }
}

// ---------------- reduce + 3x3 head conv + softmax ----------------------------
__global__ __launch_bounds__(256) void headconv_softmax_kernel(
    const float* __restrict__ part, const float* __restrict__ w_head,
    float* __restrict__ attnF)
{
    int b = blockIdx.x;
    __shared__ float A[HEADS * 1024];
    __shared__ float wsh[HEADS * HEADS * 9];
    int tid = threadIdx.x;
    if (tid < HEADS * HEADS * 9) wsh[tid] = w_head[tid];
    for (int i = tid; i < HEADS * 1024; i += 256) {
        int hd = i >> 10, rest = i & 1023;
        float s = 0.f;
        #pragma unroll
        for (int sp = 0; sp < NSPLIT; sp++)
            s += part[((size_t)sp * (BB * HEADS) + b * HEADS + hd) * 1024 + rest];
        A[i] = s;
    }
    __syncthreads();
    float cv[24];
    #pragma unroll
    for (int r = 0; r < 24; r++) {
        int i  = tid * 24 + r;
        int ho = i >> 10;
        int yx = i & 1023;
        int y = yx >> 5, x = yx & 31;
        float s = 0.f;
        for (int hi = 0; hi < HEADS; hi++) {
            const float* Ah = &A[hi * 1024];
            #pragma unroll
            for (int ky = 0; ky < 3; ky++) {
                int yy = y + ky - 1;
                if (yy < 0 || yy > 31) continue;
                #pragma unroll
                for (int kx = 0; kx < 3; kx++) {
                    int xx = x + kx - 1;
                    if (xx < 0 || xx > 31) continue;
                    s += wsh[((ho * HEADS + hi) * 3 + ky) * 3 + kx] * Ah[yy * 32 + xx];
                }
            }
        }
        cv[r] = s;
    }
    __syncthreads();
    #pragma unroll
    for (int r = 0; r < 24; r++) A[tid * 24 + r] = cv[r];
    __syncthreads();
    if (tid < HEADS * 32) {
        float* row = &A[tid * 32];
        float mx = -1e30f;
        for (int j = 0; j < 32; j++) mx = fmaxf(mx, row[j]);
        float sum = 0.f, e[32];
        for (int j = 0; j < 32; j++) { e[j] = expf(row[j] - mx); sum += e[j]; }
        float inv = 1.0f / sum;
        float* o = attnF + (size_t)b * (HEADS * 1024) + tid * 32;
        for (int j = 0; j < 32; j++) o[j] = e[j] * inv;
    }
}

// ---------------- out = attn @ v -> split bf16 token-major --------------------
__global__ __launch_bounds__(256) void av_kernel(
    const float* __restrict__ attn, const float* __restrict__ qkv,
    __nv_bfloat16* __restrict__ avs)
{
    int bh = blockIdx.y;
    int b = bh / HEADS, hd = bh % HEADS;
    __shared__ float As[32][32];
    for (int i = threadIdx.x; i < 1024; i += 256)
        ((float*)As)[i] = attn[(size_t)bh * 1024 + i];
    __syncthreads();
    int n = blockIdx.x * 256 + threadIdx.x;
    const float* v = qkv + ((size_t)b * C3 + 2 * CC + hd * CP) * HWH + n;
    float vv[32];
    #pragma unroll
    for (int d = 0; d < 32; d++) vv[d] = v[(size_t)d * HWH];
    uint32_t hp[16], lp[16];
    #pragma unroll
    for (int c2 = 0; c2 < 16; c2++) {
        float s0 = 0.f, s1 = 0.f;
        #pragma unroll
        for (int d = 0; d < 32; d++) {
            s0 = fmaf(As[2 * c2][d], vv[d], s0);
            s1 = fmaf(As[2 * c2 + 1][d], vv[d], s1);
        }
        float l0, l1;
        hp[c2] = pack2(s0, s1, l0, l1);
        lp[c2] = pack2b(l0, l1);
    }
    size_t tok = (size_t)b * HWH + n;
    uint4* dh = (uint4*)(avs + tok * 384 + hd * 32);
    uint4* dl = (uint4*)(avs + tok * 384 + 192 + hd * 32);
    #pragma unroll
    for (int q = 0; q < 4; q++) { dh[q] = ((uint4*)hp)[q]; dl[q] = ((uint4*)lp)[q]; }
}

// ---------------- spatial gate ------------------------------------------------
__global__ __launch_bounds__(256) void gate_kernel(
    const float* __restrict__ y4, const float* __restrict__ w_sa,
    const float* __restrict__ b_sa, float* __restrict__ gate)
{
    __shared__ float tile[18][18];
    __shared__ float ws[CC * 9];
    int bx = blockIdx.x & 7;
    int by = (blockIdx.x >> 3) & 7;
    int b  = blockIdx.x >> 6;
    int tx = threadIdx.x & 15, ty = threadIdx.x >> 4;
    for (int i = threadIdx.x; i < CC * 9; i += 256) ws[i] = w_sa[i];
    float acc = 0.f;
    for (int c = 0; c < CC; c++) {
        const float* ip = y4 + ((size_t)b * CC + c) * HWH;
        for (int i = threadIdx.x; i < 18 * 18; i += 256) {
            int ly = i / 18, lx = i % 18;
            int gy = by * 16 + ly - 1, gx = bx * 16 + lx - 1;
            tile[ly][lx] = (gy >= 0 && gy < HH && gx >= 0 && gx < WW)
                               ? ip[gy * WW + gx] : 0.f;
        }
        __syncthreads();
        const float* wp = &ws[c * 9];
        #pragma unroll
        for (int ky = 0; ky < 3; ky++)
            #pragma unroll
            for (int kx = 0; kx < 3; kx++)
                acc = fmaf(wp[ky * 3 + kx], tile[ty + ky][tx + kx], acc);
        __syncthreads();
    }
    int oy = by * 16 + ty, ox = bx * 16 + tx;
    gate[(size_t)b * HWH + oy * WW + ox] =
        1.0f / (1.0f + expf(-(acc + b_sa[0])));
}

// ---------------- final: out = x2 + y4 * gate ---------------------------------
__global__ __launch_bounds__(256) void final_kernel(
    const float* __restrict__ x2, const float* __restrict__ y4,
    const float* __restrict__ gate, float* __restrict__ out)
{
    int i4 = blockIdx.x * 256 + threadIdx.x;
    int elem = i4 * 4;
    int b = elem / (CC * HWH);
    int p = elem % HWH;
    float4 a = ((const float4*)x2)[i4];
    float4 y = ((const float4*)y4)[i4];
    float4 g = ((const float4*)gate)[(size_t)b * (HWH / 4) + (p >> 2)];
    float4 r;
    r.x = a.x + y.x * g.x;
    r.y = a.y + y.y * g.y;
    r.z = a.z + y.z * g.z;
    r.w = a.w + y.w * g.w;
    ((float4*)out)[i4] = r;
}

// =============================================================================
extern "C" void kernel_launch(void* const* d_in, const int* in_sizes, int n_in,
                              void* d_out, int out_size)
{
    const float* x      = (const float*)d_in[0];
    const float* g1     = (const float*)d_in[1];
    const float* b1     = (const float*)d_in[2];
    const float* w_qkv  = (const float*)d_in[3];
    const float* w_dw   = (const float*)d_in[4];
    const float* temp   = (const float*)d_in[5];
    const float* w_head = (const float*)d_in[6];
    const float* w_proj = (const float*)d_in[7];
    const float* g2     = (const float*)d_in[8];
    const float* b2     = (const float*)d_in[9];
    const float* w_fc1  = (const float*)d_in[10];
    const float* b_fc1  = (const float*)d_in[11];
    const float* w_fc2  = (const float*)d_in[12];
    const float* b_fc2  = (const float*)d_in[13];
    const float* w_sa   = (const float*)d_in[14];
    const float* b_sa   = (const float*)d_in[15];
    float* out = (float*)d_out;

    float *p_x1, *p_qkv1, *p_qkv2, *p_invn, *p_part, *p_attn, *p_x2, *p_y4, *p_gate;
    __nv_bfloat16 *p_x1s, *p_avs, *p_xns, *p_h1s, *p_wq, *p_wp, *p_w1, *p_w2;
    cudaGetSymbolAddress((void**)&p_x1,   g_x1);
    cudaGetSymbolAddress((void**)&p_x1s,  g_x1s);
    cudaGetSymbolAddress((void**)&p_qkv1, g_qkv1);
    cudaGetSymbolAddress((void**)&p_qkv2, g_qkv2);
    cudaGetSymbolAddress((void**)&p_invn, g_invn);
    cudaGetSymbolAddress((void**)&p_part, g_part);
    cudaGetSymbolAddress((void**)&p_attn, g_attn);
    cudaGetSymbolAddress((void**)&p_avs,  g_avs);
    cudaGetSymbolAddress((void**)&p_x2,   g_x2);
    cudaGetSymbolAddress((void**)&p_xns,  g_xns);
    cudaGetSymbolAddress((void**)&p_h1s,  g_h1s);
    cudaGetSymbolAddress((void**)&p_y4,   g_y4);
    cudaGetSymbolAddress((void**)&p_gate, g_gate);
    cudaGetSymbolAddress((void**)&p_wq,   g_wq);
    cudaGetSymbolAddress((void**)&p_wp,   g_wp);
    cudaGetSymbolAddress((void**)&p_w1,   g_w1);
    cudaGetSymbolAddress((void**)&p_w2,   g_w2);

    const int SMEM_G = 51200;
    cudaFuncSetAttribute(mma_gemm<192, 0>, cudaFuncAttributeMaxDynamicSharedMemorySize, SMEM_G);
    cudaFuncSetAttribute(mma_gemm<192, 1>, cudaFuncAttributeMaxDynamicSharedMemorySize, SMEM_G);
    cudaFuncSetAttribute(mma_gemm<192, 3>, cudaFuncAttributeMaxDynamicSharedMemorySize, SMEM_G);
    cudaFuncSetAttribute(mma_gemm<384, 2>, cudaFuncAttributeMaxDynamicSharedMemorySize, SMEM_G);

    // weight prep (tiny)
    prep_w<<<(C3 * CC + 255) / 256, 256>>>(w_qkv, p_wq, C3, CC);
    prep_w<<<(CC * CC + 255) / 256, 256>>>(w_proj, p_wp, CC, CC);
    prep_w<<<(HID * CC + 255) / 256, 256>>>(w_fc1, p_w1, HID, CC);
    prep_w<<<(CC * HID + 255) / 256, 256>>>(w_fc2, p_w2, CC, HID);

    // 1) LN1: x -> x1 (f32 channel-major) + x1s (split bf16 token-major)
    ln_split<true><<<dim3(HWH / 32, BB), 256>>>(x, g1, b1, p_x1, p_x1s);

    // 2) qkv GEMM: 576 out-ch = 3 N-tiles of 192
    mma_gemm<192, 0><<<dim3(NTOK / 128, 3), 256, SMEM_G>>>(
        p_x1s, p_wq, nullptr, nullptr, p_qkv1, nullptr, C3, 0, 0);

    // 3) depthwise 3x3
    dwconv_kernel<<<dim3(HWH / 256, BB * C3), 256>>>(p_qkv1, w_dw, p_qkv2);

    // 4-7) attention path
    rownorm_kernel<<<BB * 2 * CC, 256>>>(p_qkv2, p_invn);
    qk_kernel<<<dim3(BB * HEADS, NSPLIT), 256>>>(p_qkv2, p_invn, temp, p_part);
    headconv_softmax_kernel<<<BB, 256>>>(p_part, w_head, p_attn);
    av_kernel<<<dim3(HWH / 256, BB * HEADS), 256>>>(p_attn, p_qkv2, p_avs);

    // 8) proj GEMM + residual x1 -> x2
    mma_gemm<192, 3><<<dim3(NTOK / 128, 1), 256, SMEM_G>>>(
        p_avs, p_wp, nullptr, p_x1, p_x2, nullptr, CC, 0, 0);

    // 9) LN2: x2 -> xns (split only)
    ln_split<false><<<dim3(HWH / 32, BB), 256>>>(p_x2, g2, b2, nullptr, p_xns);

    // 10) fc1 GEMM + bias + gelu -> h1s (384 out = 2 N-tiles)
    mma_gemm<192, 1><<<dim3(NTOK / 128, 2), 256, SMEM_G>>>(
        p_xns, p_w1, b_fc1, nullptr, nullptr, p_h1s, 0, 2 * HID, HID);

    // 11) fc2 GEMM (K=384) + bias + gelu -> y4
    mma_gemm<384, 2><<<dim3(NTOK / 128, 1), 256, SMEM_G>>>(
        p_h1s, p_w2, b_fc2, nullptr, p_y4, nullptr, CC, 0, 0);

    // 12) gate, 13) final
    gate_kernel<<<BB * 64, 256>>>(p_y4, w_sa, b_sa, p_gate);
    final_kernel<<<(BB * CC * HWH / 4) / 256, 256>>>(p_x2, p_y4, p_gate, out);

    (void)in_sizes; (void)n_in; (void)out_size;
}

// round 8
// speedup vs baseline: 1.8364x; 1.5188x over previous
#include <cuda_runtime.h>
#include <cuda_fp16.h>
#include <math.h>
#include <stdint.h>

#define BB 4
#define CC 192
#define HH 128
#define WW 128
#define HWH (HH*WW)          // 16384
#define C3 576
#define HID 384
#define HEADS 6
#define CP 32
#define NSPLIT 8
#define NTOK (BB*HWH)        // 65536

// ---------------- scratch (device globals; allocation-free) -------------------
__device__ float  g_x1  [(size_t)BB*CC*HWH];
__device__ __half g_x1s [(size_t)NTOK*CC];
__device__ float  g_qkv1[(size_t)BB*C3*HWH];
__device__ float  g_qkv2[(size_t)BB*C3*HWH];
__device__ float  g_invn[BB*2*CC];
__device__ float  g_part[NSPLIT*BB*HEADS*CP*CP];
__device__ float  g_attn[BB*HEADS*CP*CP];
__device__ __half g_avs [(size_t)NTOK*CC];
__device__ float  g_x2  [(size_t)BB*CC*HWH];
__device__ __half g_xns [(size_t)NTOK*CC];
__device__ __half g_h1s [(size_t)NTOK*HID];
__device__ float  g_y4  [(size_t)BB*CC*HWH];
__device__ float  g_gatep[(size_t)4*NTOK];
__device__ __half g_wq  [(size_t)C3 *CC];
__device__ __half g_wp  [(size_t)CC *CC];
__device__ __half g_w1  [(size_t)HID*CC];
__device__ __half g_w2  [(size_t)CC *HID];

// ---------------- small helpers ----------------------------------------------
__device__ __forceinline__ float gelu_exact(float x) {
    return 0.5f * x * (1.0f + erff(x * 0.70710678118654752f));
}
__device__ __forceinline__ uint32_t smem_u32(const void* p) {
    uint32_t a;
    asm("{ .reg .u64 t; cvta.to.shared.u64 t, %1; cvt.u32.u64 %0, t; }"
        : "=r"(a) : "l"(p));
    return a;
}
__device__ __forceinline__ void cpa16(uint32_t dst, const void* src) {
    asm volatile("cp.async.cg.shared.global [%0], [%1], 16;" :: "r"(dst), "l"(src) : "memory");
}
__device__ __forceinline__ void mma16816(float* c, const uint32_t* a, const uint32_t* b) {
    asm volatile(
        "mma.sync.aligned.m16n8k16.row.col.f32.f16.f16.f32 "
        "{%0,%1,%2,%3}, {%4,%5,%6,%7}, {%8,%9}, {%0,%1,%2,%3};"
        : "+f"(c[0]), "+f"(c[1]), "+f"(c[2]), "+f"(c[3])
        : "r"(a[0]), "r"(a[1]), "r"(a[2]), "r"(a[3]), "r"(b[0]), "r"(b[1]));
}
#define LDMX4(r, addr)                                                          \
    asm volatile("ldmatrix.sync.aligned.m8n8.x4.shared.b16 {%0,%1,%2,%3}, [%4];" \
        : "=r"((r)[0]), "=r"((r)[1]), "=r"((r)[2]), "=r"((r)[3]) : "r"(addr))
__device__ __forceinline__ uint32_t packh2(float a, float b) {
    __half2 h = __floats2half2_rn(a, b);
    return *(uint32_t*)&h;
}

// ---------------- weight prep: [N,K] f32 -> fp16 -------------------------------
__global__ void prep_w(const float* __restrict__ src, __half* __restrict__ dst, int n)
{
    int i = blockIdx.x * 256 + threadIdx.x;
    if (i < n) dst[i] = __float2half(src[i]);
}

// ======================= warp-MMA fp16 GEMM (128 x 192 tile) ==================
// D[128 tok, 192 nch] = A[tok,K](fp16) x W[nch,K](fp16), fp32 accum.
// EPI 0: f32 channel-major   EPI 1: +bias,gelu -> fp16 token-major
// EPI 2: +bias,gelu -> f32 channel-major   EPI 3: +res -> f32 channel-major
// Dynamic smem 51200 B: A bufs 2x10240 + B bufs 2x15360 (stride AST=40 halves
// = 80 B, 16B-aligned, ldmatrix conflict-free: groups 5r mod 8 distinct).
template<int K, int EPI>
__global__ __launch_bounds__(256) void mma_gemm(
    const __half* __restrict__ Ag_, const __half* __restrict__ Wp,
    const float* __restrict__ bias, const float* __restrict__ res,
    float* __restrict__ outF, __half* __restrict__ outS,
    int outC, int nRowW)
{
    constexpr int NCH = K / 32;
    constexpr int AST = 40;
    extern __shared__ __align__(16) char sm[];
    const uint32_t smb = smem_u32(sm);
    const uint32_t sA[2] = { smb, smb + 10240 };
    const uint32_t sB[2] = { smb + 20480, smb + 35840 };
    float (*Cs)[50] = (float(*)[50])sm;

    const int tid = threadIdx.x;
    const int wid = tid >> 5, lane = tid & 31;
    const int g = lane >> 2, t2 = (lane & 3) * 2;
    const int wm = wid & 1, wn = wid >> 1;        // warp grid: 2 (M) x 4 (N)
    const size_t tok0 = (size_t)blockIdx.x * 128;
    const int n0 = blockIdx.y * 192;
    const char* Agc = (const char*)(Ag_ + tok0 * K);
    const char* Bgc = (const char*)(Wp + (size_t)n0 * K);

    const uint32_t a_lrow = (uint32_t)(wm * 64 + (lane & 15)) * (AST * 2) + ((lane >> 4) << 4);
    const uint32_t b_lrow = (uint32_t)(wn * 48 + (lane & 7) + ((lane >> 4) << 3)) * (AST * 2)
                          + (((lane >> 3) & 1) << 4);

    float acc[4][6][4];
    #pragma unroll
    for (int mi = 0; mi < 4; mi++)
        #pragma unroll
        for (int ni = 0; ni < 6; ni++)
            #pragma unroll
            for (int q = 0; q < 4; q++) acc[mi][ni][q] = 0.f;

    auto issue = [&](int kc, int buf) {
        const char* As = Agc + kc * 64;          // 32 halves = 64 B
        const char* Bs = Bgc + kc * 64;
        #pragma unroll
        for (int i = 0; i < 2; i++) {            // A: 128 rows x 4 x 16B
            int v = tid + i * 256;
            int r = v >> 2, j = v & 3;
            cpa16(sA[buf] + r * (AST * 2) + j * 16, As + (size_t)r * (2 * K) + j * 16);
        }
        #pragma unroll
        for (int i = 0; i < 3; i++) {            // B: 192 rows x 4 x 16B
            int v = tid + i * 256;
            int r = v >> 2, j = v & 3;
            cpa16(sB[buf] + r * (AST * 2) + j * 16, Bs + (size_t)r * (2 * K) + j * 16);
        }
        asm volatile("cp.async.commit_group;" ::: "memory");
    };

    issue(0, 0);
    for (int i = 0; i < NCH; i++) {
        int cb = i & 1;
        if (i + 1 < NCH) {
            issue(i + 1, cb ^ 1);
            asm volatile("cp.async.wait_group 1;" ::: "memory");
        } else {
            asm volatile("cp.async.wait_group 0;" ::: "memory");
        }
        __syncthreads();
        #pragma unroll
        for (int ks = 0; ks < 2; ks++) {
            uint32_t af[4][4], bfr[6][2];
            #pragma unroll
            for (int mi = 0; mi < 4; mi++) {
                uint32_t ad = sA[cb] + a_lrow + mi * 16 * (AST * 2) + ks * 32;
                LDMX4(af[mi], ad);
            }
            #pragma unroll
            for (int p = 0; p < 3; p++) {
                uint32_t r4[4];
                uint32_t bd = sB[cb] + b_lrow + p * 16 * (AST * 2) + ks * 32;
                LDMX4(r4, bd);
                bfr[2 * p][0] = r4[0]; bfr[2 * p][1] = r4[1];
                bfr[2 * p + 1][0] = r4[2]; bfr[2 * p + 1][1] = r4[3];
            }
            #pragma unroll
            for (int mi = 0; mi < 4; mi++)
                #pragma unroll
                for (int ni = 0; ni < 6; ni++)
                    mma16816(acc[mi][ni], af[mi], bfr[ni]);
        }
        __syncthreads();
    }

    // -------- epilogue: 4 slabs of 48 channels, staged through smem ----------
    const int bq = (int)(tok0 >> 14);
    const int tl0 = (int)(tok0 & 16383);
    for (int s = 0; s < 4; s++) {
        if (wn == s) {
            #pragma unroll
            for (int mi = 0; mi < 4; mi++)
                #pragma unroll
                for (int ni = 0; ni < 6; ni++) {
                    int m = wm * 64 + mi * 16 + g;
                    int n = ni * 8 + t2;
                    Cs[m][n]         = acc[mi][ni][0];
                    Cs[m][n + 1]     = acc[mi][ni][1];
                    Cs[m + 8][n]     = acc[mi][ni][2];
                    Cs[m + 8][n + 1] = acc[mi][ni][3];
                }
        }
        __syncthreads();
        const int chb = n0 + s * 48;
        if (EPI == 1) {
            int tokl = tid >> 1, co = (tid & 1) * 24;
            size_t tok = tok0 + tokl;
            uint32_t hp[12];
            #pragma unroll
            for (int j = 0; j < 12; j++) {
                int ch = co + 2 * j;
                float v0 = gelu_exact(Cs[tokl][ch]     + __ldg(&bias[chb + ch]));
                float v1 = gelu_exact(Cs[tokl][ch + 1] + __ldg(&bias[chb + ch + 1]));
                hp[j] = packh2(v0, v1);
            }
            uint4* dh = (uint4*)(outS + tok * nRowW + chb + co);
            #pragma unroll
            for (int q = 0; q < 3; q++) dh[q] = ((uint4*)hp)[q];
        } else {
            #pragma unroll 4
            for (int i = tid; i < 48 * 128; i += 256) {
                int ch = i >> 7, tl_ = i & 127;
                float v = Cs[tl_][ch];
                int chg = chb + ch;
                if (EPI == 2) v = gelu_exact(v + __ldg(&bias[chg]));
                if (EPI == 3) v += res[((size_t)bq * CC + chg) * HWH + tl0 + tl_];
                outF[((size_t)bq * outC + chg) * HWH + tl0 + tl_] = v;
            }
        }
        __syncthreads();
    }
}

// ---------------- LayerNorm -> f32 (opt) + fp16 token-major -------------------
template<bool F32OUT>
__global__ __launch_bounds__(256) void ln_split(
    const float* __restrict__ x, const float* __restrict__ g,
    const float* __restrict__ bta, float* __restrict__ outF,
    __half* __restrict__ outS)
{
    __shared__ float t[CC][33];
    __shared__ float s_mean[32], s_inv[32];
    const int b = blockIdx.y, p0 = blockIdx.x * 32;
    const int tid = threadIdx.x, w = tid >> 5, l = tid & 31;
    const float* xb = x + (size_t)b * CC * HWH + p0;
    for (int i = tid; i < CC * 32; i += 256) {
        int c = i >> 5, tk = i & 31;
        t[c][tk] = xb[(size_t)c * HWH + tk];
    }
    __syncthreads();
    #pragma unroll
    for (int r = 0; r < 4; r++) {
        int tk = w * 4 + r;
        float s = 0.f, ss = 0.f;
        #pragma unroll
        for (int c = l; c < CC; c += 32) { float v = t[c][tk]; s += v; ss += v * v; }
        #pragma unroll
        for (int o = 16; o; o >>= 1) {
            s  += __shfl_xor_sync(0xFFFFFFFFu, s, o);
            ss += __shfl_xor_sync(0xFFFFFFFFu, ss, o);
        }
        if (l == 0) {
            float m = s * (1.0f / CC);
            s_mean[tk] = m;
            s_inv[tk]  = rsqrtf(ss * (1.0f / CC) - m * m + 1e-5f);
        }
    }
    __syncthreads();
    if (F32OUT) {
        float* ob = outF + (size_t)b * CC * HWH + p0;
        for (int i = tid; i < CC * 32; i += 256) {
            int c = i >> 5, tk = i & 31;
            ob[(size_t)c * HWH + tk] =
                (t[c][tk] - s_mean[tk]) * s_inv[tk] * __ldg(&g[c]) + __ldg(&bta[c]);
        }
    }
    #pragma unroll
    for (int r = 0; r < 4; r++) {
        int tk = w * 4 + r;
        if (l < 24) {
            size_t tok = (size_t)b * HWH + p0 + tk;
            float m = s_mean[tk], inv = s_inv[tk];
            uint32_t hp[4];
            #pragma unroll
            for (int j = 0; j < 4; j++) {
                int c = l * 8 + 2 * j;
                float v0 = (t[c][tk]     - m) * inv * __ldg(&g[c])     + __ldg(&bta[c]);
                float v1 = (t[c + 1][tk] - m) * inv * __ldg(&g[c + 1]) + __ldg(&bta[c + 1]);
                hp[j] = packh2(v0, v1);
            }
            *(uint4*)(outS + tok * CC + l * 8) = *(uint4*)hp;
        }
    }
}

// ---------------- depthwise 3x3, pad 1 ---------------------------------------
__global__ __launch_bounds__(256) void dwconv_kernel(
    const float* __restrict__ in, const float* __restrict__ w,
    float* __restrict__ out)
{
    int p  = blockIdx.x * 256 + threadIdx.x;
    int bc = blockIdx.y;
    int c  = bc % C3;
    int y  = p >> 7, x0 = p & 127;
    const float* ip = in + (size_t)bc * HWH;
    const float* wp = w + c * 9;
    float acc = 0.f;
    #pragma unroll
    for (int ky = 0; ky < 3; ky++) {
        int yy = y + ky - 1;
        if (yy < 0 || yy >= HH) continue;
        #pragma unroll
        for (int kx = 0; kx < 3; kx++) {
            int xx = x0 + kx - 1;
            if (xx < 0 || xx >= WW) continue;
            acc += wp[ky * 3 + kx] * ip[yy * WW + xx];
        }
    }
    out[(size_t)bc * HWH + p] = acc;
}

// ---------------- q,k inverse L2 norms ---------------------------------------
__global__ __launch_bounds__(256) void rownorm_kernel(
    const float* __restrict__ qkv, float* __restrict__ invn)
{
    int b = blockIdx.x / 384;
    int c = blockIdx.x % 384;
    const float* row = qkv + ((size_t)b * C3 + c) * HWH;
    float ss = 0.f;
    for (int i = threadIdx.x; i < HWH; i += 256) { float v = row[i]; ss += v * v; }
    __shared__ float red[256];
    red[threadIdx.x] = ss;
    __syncthreads();
    for (int s = 128; s > 0; s >>= 1) {
        if (threadIdx.x < s) red[threadIdx.x] += red[threadIdx.x + s];
        __syncthreads();
    }
    if (threadIdx.x == 0)
        invn[blockIdx.x] = 1.0f / fmaxf(sqrtf(red[0]), 1e-12f);
}

// ---------------- attn partial = q k^T over split-n ---------------------------
__global__ __launch_bounds__(256) void qk_kernel(
    const float* __restrict__ qkv, const float* __restrict__ invn,
    const float* __restrict__ temp, float* __restrict__ part)
{
    int bh = blockIdx.x;
    int b = bh / HEADS, hd = bh % HEADS;
    const float* q = qkv + ((size_t)b * C3 + hd * CP) * HWH;
    const float* k = qkv + ((size_t)b * C3 + CC + hd * CP) * HWH;
    __shared__ float Qs[32][65];
    __shared__ float Ks[32][65];
    const int n0 = blockIdx.y * (HWH / NSPLIT);
    float acc[4] = {0.f, 0.f, 0.f, 0.f};
    const int c = threadIdx.x & 31;
    const int dbase = (threadIdx.x >> 5) * 4;
    for (int t = 0; t < HWH / NSPLIT; t += 64) {
        for (int i = threadIdx.x; i < 32 * 64; i += 256) {
            int r = i >> 6, col = i & 63;
            Qs[r][col] = q[(size_t)r * HWH + n0 + t + col];
            Ks[r][col] = k[(size_t)r * HWH + n0 + t + col];
        }
        __syncthreads();
        #pragma unroll 8
        for (int n = 0; n < 64; n++) {
            float qv = Qs[c][n];
            acc[0] = fmaf(qv, Ks[dbase + 0][n], acc[0]);
            acc[1] = fmaf(qv, Ks[dbase + 1][n], acc[1]);
            acc[2] = fmaf(qv, Ks[dbase + 2][n], acc[2]);
            acc[3] = fmaf(qv, Ks[dbase + 3][n], acc[3]);
        }
        __syncthreads();
    }
    float iq = invn[b * 384 + hd * CP + c];
    float tp = temp[hd];
    #pragma unroll
    for (int j = 0; j < 4; j++) {
        int d = dbase + j;
        float ik = invn[b * 384 + CC + hd * CP + d];
        part[((size_t)blockIdx.y * (BB * HEADS) + bh) * 1024 + c * 32 + d]
            = acc[j] * iq * ik * tp;
    }
}

// ---------------- reduce + 3x3 head conv + softmax ----------------------------
__global__ __launch_bounds__(256) void headconv_softmax_kernel(
    const float* __restrict__ part, const float* __restrict__ w_head,
    float* __restrict__ attnF)
{
    int b = blockIdx.x;
    __shared__ float A[HEADS * 1024];
    __shared__ float wsh[HEADS * HEADS * 9];
    int tid = threadIdx.x;
    if (tid < HEADS * HEADS * 9) wsh[tid] = w_head[tid];
    for (int i = tid; i < HEADS * 1024; i += 256) {
        int hd = i >> 10, rest = i & 1023;
        float s = 0.f;
        #pragma unroll
        for (int sp = 0; sp < NSPLIT; sp++)
            s += part[((size_t)sp * (BB * HEADS) + b * HEADS + hd) * 1024 + rest];
        A[i] = s;
    }
    __syncthreads();
    float cv[24];
    #pragma unroll
    for (int r = 0; r < 24; r++) {
        int i  = tid * 24 + r;
        int ho = i >> 10;
        int yx = i & 1023;
        int y = yx >> 5, x = yx & 31;
        float s = 0.f;
        for (int hi = 0; hi < HEADS; hi++) {
            const float* Ah = &A[hi * 1024];
            #pragma unroll
            for (int ky = 0; ky < 3; ky++) {
                int yy = y + ky - 1;
                if (yy < 0 || yy > 31) continue;
                #pragma unroll
                for (int kx = 0; kx < 3; kx++) {
                    int xx = x + kx - 1;
                    if (xx < 0 || xx > 31) continue;
                    s += wsh[((ho * HEADS + hi) * 3 + ky) * 3 + kx] * Ah[yy * 32 + xx];
                }
            }
        }
        cv[r] = s;
    }
    __syncthreads();
    #pragma unroll
    for (int r = 0; r < 24; r++) A[tid * 24 + r] = cv[r];
    __syncthreads();
    if (tid < HEADS * 32) {
        float* row = &A[tid * 32];
        float mx = -1e30f;
        for (int j = 0; j < 32; j++) mx = fmaxf(mx, row[j]);
        float sum = 0.f, e[32];
        for (int j = 0; j < 32; j++) { e[j] = expf(row[j] - mx); sum += e[j]; }
        float inv = 1.0f / sum;
        float* o = attnF + (size_t)b * (HEADS * 1024) + tid * 32;
        for (int j = 0; j < 32; j++) o[j] = e[j] * inv;
    }
}

// ---------------- out = attn @ v -> fp16 token-major ---------------------------
__global__ __launch_bounds__(256) void av_kernel(
    const float* __restrict__ attn, const float* __restrict__ qkv,
    __half* __restrict__ avs)
{
    int bh = blockIdx.y;
    int b = bh / HEADS, hd = bh % HEADS;
    __shared__ float As[32][32];
    for (int i = threadIdx.x; i < 1024; i += 256)
        ((float*)As)[i] = attn[(size_t)bh * 1024 + i];
    __syncthreads();
    int n = blockIdx.x * 256 + threadIdx.x;
    const float* v = qkv + ((size_t)b * C3 + 2 * CC + hd * CP) * HWH + n;
    float vv[32];
    #pragma unroll
    for (int d = 0; d < 32; d++) vv[d] = v[(size_t)d * HWH];
    uint32_t hp[16];
    #pragma unroll
    for (int c2 = 0; c2 < 16; c2++) {
        float s0 = 0.f, s1 = 0.f;
        #pragma unroll
        for (int d = 0; d < 32; d++) {
            s0 = fmaf(As[2 * c2][d], vv[d], s0);
            s1 = fmaf(As[2 * c2 + 1][d], vv[d], s1);
        }
        hp[c2] = packh2(s0, s1);
    }
    size_t tok = (size_t)b * HWH + n;
    uint4* dh = (uint4*)(avs + tok * CC + hd * 32);
    #pragma unroll
    for (int q = 0; q < 4; q++) dh[q] = ((uint4*)hp)[q];
}

// ---------------- spatial gate partials: 48 channels per block ----------------
__global__ __launch_bounds__(256) void gate_kernel(
    const float* __restrict__ y4, const float* __restrict__ w_sa,
    float* __restrict__ gatep)
{
    __shared__ float tile[18][18];
    __shared__ float ws[48 * 9];
    int bx = blockIdx.x & 7;
    int by = (blockIdx.x >> 3) & 7;
    int cs = (blockIdx.x >> 6) & 3;
    int b  = blockIdx.x >> 8;
    int tx = threadIdx.x & 15, ty = threadIdx.x >> 4;
    for (int i = threadIdx.x; i < 48 * 9; i += 256) ws[i] = w_sa[cs * 48 * 9 + i];
    float acc = 0.f;
    for (int c = 0; c < 48; c++) {
        const float* ip = y4 + ((size_t)b * CC + cs * 48 + c) * HWH;
        for (int i = threadIdx.x; i < 18 * 18; i += 256) {
            int ly = i / 18, lx = i % 18;
            int gy = by * 16 + ly - 1, gx = bx * 16 + lx - 1;
            tile[ly][lx] = (gy >= 0 && gy < HH && gx >= 0 && gx < WW)
                               ? ip[gy * WW + gx] : 0.f;
        }
        __syncthreads();
        const float* wp = &ws[c * 9];
        #pragma unroll
        for (int ky = 0; ky < 3; ky++)
            #pragma unroll
            for (int kx = 0; kx < 3; kx++)
                acc = fmaf(wp[ky * 3 + kx], tile[ty + ky][tx + kx], acc);
        __syncthreads();
    }
    int oy = by * 16 + ty, ox = bx * 16 + tx;
    gatep[(size_t)cs * NTOK + (size_t)b * HWH + oy * WW + ox] = acc;
}

// ---------------- final: out = x2 + y4 * sigmoid(sum partials + b) ------------
__global__ __launch_bounds__(256) void final_kernel(
    const float* __restrict__ x2, const float* __restrict__ y4,
    const float* __restrict__ gatep, const float* __restrict__ b_sa,
    float* __restrict__ out)
{
    int i4 = blockIdx.x * 256 + threadIdx.x;
    int elem = i4 * 4;
    int b = elem / (CC * HWH);
    int p = elem % HWH;
    float4 a = ((const float4*)x2)[i4];
    float4 y = ((const float4*)y4)[i4];
    size_t gp = (size_t)b * HWH + p;
    float4 s0 = *(const float4*)(gatep + gp);
    float4 s1 = *(const float4*)(gatep + NTOK + gp);
    float4 s2 = *(const float4*)(gatep + 2 * (size_t)NTOK + gp);
    float4 s3 = *(const float4*)(gatep + 3 * (size_t)NTOK + gp);
    float bs = b_sa[0];
    float g0 = 1.0f / (1.0f + expf(-(s0.x + s1.x + s2.x + s3.x + bs)));
    float g1 = 1.0f / (1.0f + expf(-(s0.y + s1.y + s2.y + s3.y + bs)));
    float g2 = 1.0f / (1.0f + expf(-(s0.z + s1.z + s2.z + s3.z + bs)));
    float g3 = 1.0f / (1.0f + expf(-(s0.w + s1.w + s2.w + s3.w + bs)));
    float4 r;
    r.x = a.x + y.x * g0;
    r.y = a.y + y.y * g1;
    r.z = a.z + y.z * g2;
    r.w = a.w + y.w * g3;
    ((float4*)out)[i4] = r;
}

// =============================================================================
extern "C" void kernel_launch(void* const* d_in, const int* in_sizes, int n_in,
                              void* d_out, int out_size)
{
    const float* x      = (const float*)d_in[0];
    const float* g1     = (const float*)d_in[1];
    const float* b1     = (const float*)d_in[2];
    const float* w_qkv  = (const float*)d_in[3];
    const float* w_dw   = (const float*)d_in[4];
    const float* temp   = (const float*)d_in[5];
    const float* w_head = (const float*)d_in[6];
    const float* w_proj = (const float*)d_in[7];
    const float* g2     = (const float*)d_in[8];
    const float* b2     = (const float*)d_in[9];
    const float* w_fc1  = (const float*)d_in[10];
    const float* b_fc1  = (const float*)d_in[11];
    const float* w_fc2  = (const float*)d_in[12];
    const float* b_fc2  = (const float*)d_in[13];
    const float* w_sa   = (const float*)d_in[14];
    const float* b_sa   = (const float*)d_in[15];
    float* out = (float*)d_out;

    float *p_x1, *p_qkv1, *p_qkv2, *p_invn, *p_part, *p_attn, *p_x2, *p_y4, *p_gatep;
    __half *p_x1s, *p_avs, *p_xns, *p_h1s, *p_wq, *p_wp, *p_w1, *p_w2;
    cudaGetSymbolAddress((void**)&p_x1,   g_x1);
    cudaGetSymbolAddress((void**)&p_x1s,  g_x1s);
    cudaGetSymbolAddress((void**)&p_qkv1, g_qkv1);
    cudaGetSymbolAddress((void**)&p_qkv2, g_qkv2);
    cudaGetSymbolAddress((void**)&p_invn, g_invn);
    cudaGetSymbolAddress((void**)&p_part, g_part);
    cudaGetSymbolAddress((void**)&p_attn, g_attn);
    cudaGetSymbolAddress((void**)&p_avs,  g_avs);
    cudaGetSymbolAddress((void**)&p_x2,   g_x2);
    cudaGetSymbolAddress((void**)&p_xns,  g_xns);
    cudaGetSymbolAddress((void**)&p_h1s,  g_h1s);
    cudaGetSymbolAddress((void**)&p_y4,   g_y4);
    cudaGetSymbolAddress((void**)&p_gatep, g_gatep);
    cudaGetSymbolAddress((void**)&p_wq,   g_wq);
    cudaGetSymbolAddress((void**)&p_wp,   g_wp);
    cudaGetSymbolAddress((void**)&p_w1,   g_w1);
    cudaGetSymbolAddress((void**)&p_w2,   g_w2);

    const int SMEM_G = 51200;
    cudaFuncSetAttribute(mma_gemm<192, 0>, cudaFuncAttributeMaxDynamicSharedMemorySize, SMEM_G);
    cudaFuncSetAttribute(mma_gemm<192, 1>, cudaFuncAttributeMaxDynamicSharedMemorySize, SMEM_G);
    cudaFuncSetAttribute(mma_gemm<192, 3>, cudaFuncAttributeMaxDynamicSharedMemorySize, SMEM_G);
    cudaFuncSetAttribute(mma_gemm<384, 2>, cudaFuncAttributeMaxDynamicSharedMemorySize, SMEM_G);

    // weight prep (tiny)
    prep_w<<<(C3 * CC + 255) / 256, 256>>>(w_qkv, p_wq, C3 * CC);
    prep_w<<<(CC * CC + 255) / 256, 256>>>(w_proj, p_wp, CC * CC);
    prep_w<<<(HID * CC + 255) / 256, 256>>>(w_fc1, p_w1, HID * CC);
    prep_w<<<(CC * HID + 255) / 256, 256>>>(w_fc2, p_w2, CC * HID);

    // 1) LN1: x -> x1 (f32 channel-major) + x1s (fp16 token-major)
    ln_split<true><<<dim3(HWH / 32, BB), 256>>>(x, g1, b1, p_x1, p_x1s);

    // 2) qkv GEMM: 576 out-ch = 3 N-tiles of 192
    mma_gemm<192, 0><<<dim3(NTOK / 128, 3), 256, SMEM_G>>>(
        p_x1s, p_wq, nullptr, nullptr, p_qkv1, nullptr, C3, 0);

    // 3) depthwise 3x3
    dwconv_kernel<<<dim3(HWH / 256, BB * C3), 256>>>(p_qkv1, w_dw, p_qkv2);

    // 4-7) attention path
    rownorm_kernel<<<BB * 2 * CC, 256>>>(p_qkv2, p_invn);
    qk_kernel<<<dim3(BB * HEADS, NSPLIT), 256>>>(p_qkv2, p_invn, temp, p_part);
    headconv_softmax_kernel<<<BB, 256>>>(p_part, w_head, p_attn);
    av_kernel<<<dim3(HWH / 256, BB * HEADS), 256>>>(p_attn, p_qkv2, p_avs);

    // 8) proj GEMM + residual x1 -> x2
    mma_gemm<192, 3><<<dim3(NTOK / 128, 1), 256, SMEM_G>>>(
        p_avs, p_wp, nullptr, p_x1, p_x2, nullptr, CC, 0);

    // 9) LN2: x2 -> xns (fp16 only)
    ln_split<false><<<dim3(HWH / 32, BB), 256>>>(p_x2, g2, b2, nullptr, p_xns);

    // 10) fc1 GEMM + bias + gelu -> h1s (384 out = 2 N-tiles)
    mma_gemm<192, 1><<<dim3(NTOK / 128, 2), 256, SMEM_G>>>(
        p_xns, p_w1, b_fc1, nullptr, nullptr, p_h1s, 0, HID);

    // 11) fc2 GEMM (K=384) + bias + gelu -> y4
    mma_gemm<384, 2><<<dim3(NTOK / 128, 1), 256, SMEM_G>>>(
        p_h1s, p_w2, b_fc2, nullptr, p_y4, nullptr, CC, 0);

    // 12) gate partials (4-way channel split), 13) final combine
    gate_kernel<<<BB * 64 * 4, 256>>>(p_y4, w_sa, p_gatep);
    final_kernel<<<(BB * CC * HWH / 4) / 256, 256>>>(p_x2, p_y4, p_gatep, b_sa, out);

    (void)in_sizes; (void)n_in; (void)out_size;
}

// round 9
// speedup vs baseline: 1.9671x; 1.0712x over previous
#include <cuda_runtime.h>
#include <cuda_fp16.h>
#include <math.h>
#include <stdint.h>

#define BB 4
#define CC 192
#define HH 128
#define WW 128
#define HWH (HH*WW)          // 16384
#define C3 576
#define HID 384
#define HEADS 6
#define CP 32
#define NSPLIT 8
#define NTOK (BB*HWH)        // 65536

// ---------------- scratch (device globals; allocation-free) -------------------
__device__ float  g_x1  [(size_t)BB*CC*HWH];
__device__ __half g_x1s [(size_t)NTOK*CC];
__device__ __half g_qkv1[(size_t)BB*C3*HWH];
__device__ __half g_qkv2[(size_t)BB*C3*HWH];
__device__ float  g_invn[BB*2*CC];
__device__ float  g_part[NSPLIT*BB*HEADS*CP*CP];
__device__ float  g_attn[BB*HEADS*CP*CP];
__device__ __half g_avs [(size_t)NTOK*CC];
__device__ float  g_x2  [(size_t)BB*CC*HWH];
__device__ __half g_xns [(size_t)NTOK*CC];
__device__ __half g_h1s [(size_t)NTOK*HID];
__device__ __half g_y4  [(size_t)BB*CC*HWH];
__device__ float  g_gatep[(size_t)4*NTOK];
__device__ __half g_wq  [(size_t)C3 *CC];
__device__ __half g_wp  [(size_t)CC *CC];
__device__ __half g_w1  [(size_t)HID*CC];
__device__ __half g_w2  [(size_t)CC *HID];

// ---------------- small helpers ----------------------------------------------
__device__ __forceinline__ float gelu_exact(float x) {
    return 0.5f * x * (1.0f + erff(x * 0.70710678118654752f));
}
__device__ __forceinline__ uint32_t smem_u32(const void* p) {
    uint32_t a;
    asm("{ .reg .u64 t; cvta.to.shared.u64 t, %1; cvt.u32.u64 %0, t; }"
        : "=r"(a) : "l"(p));
    return a;
}
__device__ __forceinline__ void cpa16(uint32_t dst, const void* src) {
    asm volatile("cp.async.cg.shared.global [%0], [%1], 16;" :: "r"(dst), "l"(src) : "memory");
}
__device__ __forceinline__ void mma16816(float* c, const uint32_t* a, const uint32_t* b) {
    asm volatile(
        "mma.sync.aligned.m16n8k16.row.col.f32.f16.f16.f32 "
        "{%0,%1,%2,%3}, {%4,%5,%6,%7}, {%8,%9}, {%0,%1,%2,%3};"
        : "+f"(c[0]), "+f"(c[1]), "+f"(c[2]), "+f"(c[3])
        : "r"(a[0]), "r"(a[1]), "r"(a[2]), "r"(a[3]), "r"(b[0]), "r"(b[1]));
}
#define LDMX4(r, addr)                                                          \
    asm volatile("ldmatrix.sync.aligned.m8n8.x4.shared.b16 {%0,%1,%2,%3}, [%4];" \
        : "=r"((r)[0]), "=r"((r)[1]), "=r"((r)[2]), "=r"((r)[3]) : "r"(addr))
__device__ __forceinline__ uint32_t packh2(float a, float b) {
    __half2 h = __floats2half2_rn(a, b);
    return *(uint32_t*)&h;
}

// ---------------- weight prep: [N,K] f32 -> fp16 -------------------------------
__global__ void prep_w(const float* __restrict__ src, __half* __restrict__ dst, int n)
{
    int i = blockIdx.x * 256 + threadIdx.x;
    if (i < n) dst[i] = __float2half(src[i]);
}

// ======================= warp-MMA fp16 GEMM (128 x 192 tile) ==================
// D[128 tok, 192 nch] = A[tok,K](fp16) x W[nch,K](fp16), fp32 accum.
// EPI 0: fp16 channel-major    EPI 1: +bias,gelu -> fp16 token-major
// EPI 2: +bias,gelu -> fp16 channel-major   EPI 3: +res(f32) -> f32 channel-major
// Dynamic smem 76800 B: 3-stage A bufs 3x10240 + B bufs 3x15360 (AST=40 halves
// = 80 B stride, 16B-aligned, ldmatrix conflict-free: groups 5r mod 8 distinct).
template<int K, int EPI>
__global__ __launch_bounds__(256) void mma_gemm(
    const __half* __restrict__ Ag_, const __half* __restrict__ Wp,
    const float* __restrict__ bias, const float* __restrict__ res,
    float* __restrict__ outF, __half* __restrict__ outH,
    __half* __restrict__ outS, int outC, int nRowW)
{
    constexpr int NCH = K / 32;
    constexpr int AST = 40;
    extern __shared__ __align__(16) char sm[];
    const uint32_t smb = smem_u32(sm);
    const uint32_t sA[3] = { smb, smb + 10240, smb + 20480 };
    const uint32_t sB[3] = { smb + 30720, smb + 46080, smb + 61440 };
    float (*Cs)[50] = (float(*)[50])sm;

    const int tid = threadIdx.x;
    const int wid = tid >> 5, lane = tid & 31;
    const int g = lane >> 2, t2 = (lane & 3) * 2;
    const int wm = wid & 1, wn = wid >> 1;        // warp grid: 2 (M) x 4 (N)
    const size_t tok0 = (size_t)blockIdx.x * 128;
    const int n0 = blockIdx.y * 192;
    const char* Agc = (const char*)(Ag_ + tok0 * K);
    const char* Bgc = (const char*)(Wp + (size_t)n0 * K);

    const uint32_t a_lrow = (uint32_t)(wm * 64 + (lane & 15)) * (AST * 2) + ((lane >> 4) << 4);
    const uint32_t b_lrow = (uint32_t)(wn * 48 + (lane & 7) + ((lane >> 4) << 3)) * (AST * 2)
                          + (((lane >> 3) & 1) << 4);

    float acc[4][6][4];
    #pragma unroll
    for (int mi = 0; mi < 4; mi++)
        #pragma unroll
        for (int ni = 0; ni < 6; ni++)
            #pragma unroll
            for (int q = 0; q < 4; q++) acc[mi][ni][q] = 0.f;

    auto issue = [&](int kc, int buf) {
        const char* As = Agc + kc * 64;          // 32 halves = 64 B
        const char* Bs = Bgc + kc * 64;
        #pragma unroll
        for (int i = 0; i < 2; i++) {            // A: 128 rows x 4 x 16B
            int v = tid + i * 256;
            int r = v >> 2, j = v & 3;
            cpa16(sA[buf] + r * (AST * 2) + j * 16, As + (size_t)r * (2 * K) + j * 16);
        }
        #pragma unroll
        for (int i = 0; i < 3; i++) {            // B: 192 rows x 4 x 16B
            int v = tid + i * 256;
            int r = v >> 2, j = v & 3;
            cpa16(sB[buf] + r * (AST * 2) + j * 16, Bs + (size_t)r * (2 * K) + j * 16);
        }
        asm volatile("cp.async.commit_group;" ::: "memory");
    };

    issue(0, 0);
    issue(1, 1);
    for (int i = 0; i < NCH; i++) {
        int cb = i % 3;
        if (i + 2 < NCH) {
            issue(i + 2, (i + 2) % 3);
            asm volatile("cp.async.wait_group 2;" ::: "memory");
        } else if (i + 1 < NCH) {
            asm volatile("cp.async.wait_group 1;" ::: "memory");
        } else {
            asm volatile("cp.async.wait_group 0;" ::: "memory");
        }
        __syncthreads();
        #pragma unroll
        for (int ks = 0; ks < 2; ks++) {
            uint32_t af[4][4], bfr[6][2];
            #pragma unroll
            for (int mi = 0; mi < 4; mi++) {
                uint32_t ad = sA[cb] + a_lrow + mi * 16 * (AST * 2) + ks * 32;
                LDMX4(af[mi], ad);
            }
            #pragma unroll
            for (int p = 0; p < 3; p++) {
                uint32_t r4[4];
                uint32_t bd = sB[cb] + b_lrow + p * 16 * (AST * 2) + ks * 32;
                LDMX4(r4, bd);
                bfr[2 * p][0] = r4[0]; bfr[2 * p][1] = r4[1];
                bfr[2 * p + 1][0] = r4[2]; bfr[2 * p + 1][1] = r4[3];
            }
            #pragma unroll
            for (int mi = 0; mi < 4; mi++)
                #pragma unroll
                for (int ni = 0; ni < 6; ni++)
                    mma16816(acc[mi][ni], af[mi], bfr[ni]);
        }
        __syncthreads();
    }

    // -------- epilogue: 4 slabs of 48 channels, staged through smem ----------
    const int bq = (int)(tok0 >> 14);
    const int tl0 = (int)(tok0 & 16383);
    for (int s = 0; s < 4; s++) {
        if (wn == s) {
            #pragma unroll
            for (int mi = 0; mi < 4; mi++)
                #pragma unroll
                for (int ni = 0; ni < 6; ni++) {
                    int m = wm * 64 + mi * 16 + g;
                    int n = ni * 8 + t2;
                    Cs[m][n]         = acc[mi][ni][0];
                    Cs[m][n + 1]     = acc[mi][ni][1];
                    Cs[m + 8][n]     = acc[mi][ni][2];
                    Cs[m + 8][n + 1] = acc[mi][ni][3];
                }
        }
        __syncthreads();
        const int chb = n0 + s * 48;
        if (EPI == 1) {
            int tokl = tid >> 1, co = (tid & 1) * 24;
            size_t tok = tok0 + tokl;
            uint32_t hp[12];
            #pragma unroll
            for (int j = 0; j < 12; j++) {
                int ch = co + 2 * j;
                float v0 = gelu_exact(Cs[tokl][ch]     + __ldg(&bias[chb + ch]));
                float v1 = gelu_exact(Cs[tokl][ch + 1] + __ldg(&bias[chb + ch + 1]));
                hp[j] = packh2(v0, v1);
            }
            uint4* dh = (uint4*)(outS + tok * nRowW + chb + co);
            #pragma unroll
            for (int q = 0; q < 3; q++) dh[q] = ((uint4*)hp)[q];
        } else {
            #pragma unroll 4
            for (int i = tid; i < 48 * 128; i += 256) {
                int ch = i >> 7, tl_ = i & 127;
                float v = Cs[tl_][ch];
                int chg = chb + ch;
                size_t idx = ((size_t)bq * outC + chg) * HWH + tl0 + tl_;
                if (EPI == 3) {
                    v += res[idx];
                    outF[idx] = v;
                } else {
                    if (EPI == 2) v = gelu_exact(v + __ldg(&bias[chg]));
                    outH[idx] = __float2half(v);
                }
            }
        }
        __syncthreads();
    }
}

// ---------------- LayerNorm -> f32 (opt) + fp16 token-major -------------------
template<bool F32OUT>
__global__ __launch_bounds__(256) void ln_split(
    const float* __restrict__ x, const float* __restrict__ g,
    const float* __restrict__ bta, float* __restrict__ outF,
    __half* __restrict__ outS)
{
    __shared__ float t[CC][33];
    __shared__ float s_mean[32], s_inv[32];
    const int b = blockIdx.y, p0 = blockIdx.x * 32;
    const int tid = threadIdx.x, w = tid >> 5, l = tid & 31;
    const float* xb = x + (size_t)b * CC * HWH + p0;
    for (int i = tid; i < CC * 32; i += 256) {
        int c = i >> 5, tk = i & 31;
        t[c][tk] = xb[(size_t)c * HWH + tk];
    }
    __syncthreads();
    #pragma unroll
    for (int r = 0; r < 4; r++) {
        int tk = w * 4 + r;
        float s = 0.f, ss = 0.f;
        #pragma unroll
        for (int c = l; c < CC; c += 32) { float v = t[c][tk]; s += v; ss += v * v; }
        #pragma unroll
        for (int o = 16; o; o >>= 1) {
            s  += __shfl_xor_sync(0xFFFFFFFFu, s, o);
            ss += __shfl_xor_sync(0xFFFFFFFFu, ss, o);
        }
        if (l == 0) {
            float m = s * (1.0f / CC);
            s_mean[tk] = m;
            s_inv[tk]  = rsqrtf(ss * (1.0f / CC) - m * m + 1e-5f);
        }
    }
    __syncthreads();
    if (F32OUT) {
        float* ob = outF + (size_t)b * CC * HWH + p0;
        for (int i = tid; i < CC * 32; i += 256) {
            int c = i >> 5, tk = i & 31;
            ob[(size_t)c * HWH + tk] =
                (t[c][tk] - s_mean[tk]) * s_inv[tk] * __ldg(&g[c]) + __ldg(&bta[c]);
        }
    }
    #pragma unroll
    for (int r = 0; r < 4; r++) {
        int tk = w * 4 + r;
        if (l < 24) {
            size_t tok = (size_t)b * HWH + p0 + tk;
            float m = s_mean[tk], inv = s_inv[tk];
            uint32_t hp[4];
            #pragma unroll
            for (int j = 0; j < 4; j++) {
                int c = l * 8 + 2 * j;
                float v0 = (t[c][tk]     - m) * inv * __ldg(&g[c])     + __ldg(&bta[c]);
                float v1 = (t[c + 1][tk] - m) * inv * __ldg(&g[c + 1]) + __ldg(&bta[c + 1]);
                hp[j] = packh2(v0, v1);
            }
            *(uint4*)(outS + tok * CC + l * 8) = *(uint4*)hp;
        }
    }
}

// ---------------- depthwise 3x3, pad 1 (fp16 in/out, fp32 math) --------------
__global__ __launch_bounds__(256) void dwconv_kernel(
    const __half* __restrict__ in, const float* __restrict__ w,
    __half* __restrict__ out)
{
    int p  = blockIdx.x * 256 + threadIdx.x;
    int bc = blockIdx.y;
    int c  = bc % C3;
    int y  = p >> 7, x0 = p & 127;
    const __half* ip = in + (size_t)bc * HWH;
    const float* wp = w + c * 9;
    float acc = 0.f;
    #pragma unroll
    for (int ky = 0; ky < 3; ky++) {
        int yy = y + ky - 1;
        if (yy < 0 || yy >= HH) continue;
        #pragma unroll
        for (int kx = 0; kx < 3; kx++) {
            int xx = x0 + kx - 1;
            if (xx < 0 || xx >= WW) continue;
            acc += wp[ky * 3 + kx] * __half2float(ip[yy * WW + xx]);
        }
    }
    out[(size_t)bc * HWH + p] = __float2half(acc);
}

// ---------------- q,k inverse L2 norms (fp16 rows) -----------------------------
__global__ __launch_bounds__(256) void rownorm_kernel(
    const __half* __restrict__ qkv, float* __restrict__ invn)
{
    int b = blockIdx.x / 384;
    int c = blockIdx.x % 384;
    const __half2* row = (const __half2*)(qkv + ((size_t)b * C3 + c) * HWH);
    float ss = 0.f;
    for (int i = threadIdx.x; i < HWH / 2; i += 256) {
        float2 f = __half22float2(row[i]);
        ss += f.x * f.x + f.y * f.y;
    }
    __shared__ float red[256];
    red[threadIdx.x] = ss;
    __syncthreads();
    for (int s = 128; s > 0; s >>= 1) {
        if (threadIdx.x < s) red[threadIdx.x] += red[threadIdx.x + s];
        __syncthreads();
    }
    if (threadIdx.x == 0)
        invn[blockIdx.x] = 1.0f / fmaxf(sqrtf(red[0]), 1e-12f);
}

// ---------------- attn partial = q k^T over split-n (fp16 input) --------------
__global__ __launch_bounds__(256) void qk_kernel(
    const __half* __restrict__ qkv, const float* __restrict__ invn,
    const float* __restrict__ temp, float* __restrict__ part)
{
    int bh = blockIdx.x;
    int b = bh / HEADS, hd = bh % HEADS;
    const __half2* q2 = (const __half2*)(qkv + ((size_t)b * C3 + hd * CP) * HWH);
    const __half2* k2 = (const __half2*)(qkv + ((size_t)b * C3 + CC + hd * CP) * HWH);
    __shared__ float Qs[32][65];
    __shared__ float Ks[32][65];
    const int n0 = blockIdx.y * (HWH / NSPLIT);
    float acc[4] = {0.f, 0.f, 0.f, 0.f};
    const int c = threadIdx.x & 31;
    const int dbase = (threadIdx.x >> 5) * 4;
    for (int t = 0; t < HWH / NSPLIT; t += 64) {
        int base2 = (n0 + t) >> 1;
        for (int i = threadIdx.x; i < 32 * 32; i += 256) {
            int r = i >> 5, c2 = i & 31;
            float2 fq = __half22float2(q2[(size_t)r * (HWH / 2) + base2 + c2]);
            float2 fk = __half22float2(k2[(size_t)r * (HWH / 2) + base2 + c2]);
            Qs[r][2 * c2] = fq.x; Qs[r][2 * c2 + 1] = fq.y;
            Ks[r][2 * c2] = fk.x; Ks[r][2 * c2 + 1] = fk.y;
        }
        __syncthreads();
        #pragma unroll 8
        for (int n = 0; n < 64; n++) {
            float qv = Qs[c][n];
            acc[0] = fmaf(qv, Ks[dbase + 0][n], acc[0]);
            acc[1] = fmaf(qv, Ks[dbase + 1][n], acc[1]);
            acc[2] = fmaf(qv, Ks[dbase + 2][n], acc[2]);
            acc[3] = fmaf(qv, Ks[dbase + 3][n], acc[3]);
        }
        __syncthreads();
    }
    float iq = invn[b * 384 + hd * CP + c];
    float tp = temp[hd];
    #pragma unroll
    for (int j = 0; j < 4; j++) {
        int d = dbase + j;
        float ik = invn[b * 384 + CC + hd * CP + d];
        part[((size_t)blockIdx.y * (BB * HEADS) + bh) * 1024 + c * 32 + d]
            = acc[j] * iq * ik * tp;
    }
}

// ---------------- reduce + 3x3 head conv + softmax ----------------------------
__global__ __launch_bounds__(256) void headconv_softmax_kernel(
    const float* __restrict__ part, const float* __restrict__ w_head,
    float* __restrict__ attnF)
{
    int b = blockIdx.x;
    __shared__ float A[HEADS * 1024];
    __shared__ float wsh[HEADS * HEADS * 9];
    int tid = threadIdx.x;
    if (tid < HEADS * HEADS * 9) wsh[tid] = w_head[tid];
    for (int i = tid; i < HEADS * 1024; i += 256) {
        int hd = i >> 10, rest = i & 1023;
        float s = 0.f;
        #pragma unroll
        for (int sp = 0; sp < NSPLIT; sp++)
            s += part[((size_t)sp * (BB * HEADS) + b * HEADS + hd) * 1024 + rest];
        A[i] = s;
    }
    __syncthreads();
    float cv[24];
    #pragma unroll
    for (int r = 0; r < 24; r++) {
        int i  = tid * 24 + r;
        int ho = i >> 10;
        int yx = i & 1023;
        int y = yx >> 5, x = yx & 31;
        float s = 0.f;
        for (int hi = 0; hi < HEADS; hi++) {
            const float* Ah = &A[hi * 1024];
            #pragma unroll
            for (int ky = 0; ky < 3; ky++) {
                int yy = y + ky - 1;
                if (yy < 0 || yy > 31) continue;
                #pragma unroll
                for (int kx = 0; kx < 3; kx++) {
                    int xx = x + kx - 1;
                    if (xx < 0 || xx > 31) continue;
                    s += wsh[((ho * HEADS + hi) * 3 + ky) * 3 + kx] * Ah[yy * 32 + xx];
                }
            }
        }
        cv[r] = s;
    }
    __syncthreads();
    #pragma unroll
    for (int r = 0; r < 24; r++) A[tid * 24 + r] = cv[r];
    __syncthreads();
    if (tid < HEADS * 32) {
        float* row = &A[tid * 32];
        float mx = -1e30f;
        for (int j = 0; j < 32; j++) mx = fmaxf(mx, row[j]);
        float sum = 0.f, e[32];
        for (int j = 0; j < 32; j++) { e[j] = expf(row[j] - mx); sum += e[j]; }
        float inv = 1.0f / sum;
        float* o = attnF + (size_t)b * (HEADS * 1024) + tid * 32;
        for (int j = 0; j < 32; j++) o[j] = e[j] * inv;
    }
}

// ---------------- out = attn @ v -> fp16 token-major ---------------------------
__global__ __launch_bounds__(256) void av_kernel(
    const float* __restrict__ attn, const __half* __restrict__ qkv,
    __half* __restrict__ avs)
{
    int bh = blockIdx.y;
    int b = bh / HEADS, hd = bh % HEADS;
    __shared__ float As[32][32];
    for (int i = threadIdx.x; i < 1024; i += 256)
        ((float*)As)[i] = attn[(size_t)bh * 1024 + i];
    __syncthreads();
    int n = blockIdx.x * 256 + threadIdx.x;
    const __half* v = qkv + ((size_t)b * C3 + 2 * CC + hd * CP) * HWH + n;
    float vv[32];
    #pragma unroll
    for (int d = 0; d < 32; d++) vv[d] = __half2float(v[(size_t)d * HWH]);
    uint32_t hp[16];
    #pragma unroll
    for (int c2 = 0; c2 < 16; c2++) {
        float s0 = 0.f, s1 = 0.f;
        #pragma unroll
        for (int d = 0; d < 32; d++) {
            s0 = fmaf(As[2 * c2][d], vv[d], s0);
            s1 = fmaf(As[2 * c2 + 1][d], vv[d], s1);
        }
        hp[c2] = packh2(s0, s1);
    }
    size_t tok = (size_t)b * HWH + n;
    uint4* dh = (uint4*)(avs + tok * CC + hd * 32);
    #pragma unroll
    for (int q = 0; q < 4; q++) dh[q] = ((uint4*)hp)[q];
}

// ---------------- spatial gate partials: 48 channels per block ----------------
__global__ __launch_bounds__(256) void gate_kernel(
    const __half* __restrict__ y4, const float* __restrict__ w_sa,
    float* __restrict__ gatep)
{
    __shared__ float tile[18][18];
    __shared__ float ws[48 * 9];
    int bx = blockIdx.x & 7;
    int by = (blockIdx.x >> 3) & 7;
    int cs = (blockIdx.x >> 6) & 3;
    int b  = blockIdx.x >> 8;
    int tx = threadIdx.x & 15, ty = threadIdx.x >> 4;
    for (int i = threadIdx.x; i < 48 * 9; i += 256) ws[i] = w_sa[cs * 48 * 9 + i];
    float acc = 0.f;
    for (int c = 0; c < 48; c++) {
        const __half* ip = y4 + ((size_t)b * CC + cs * 48 + c) * HWH;
        for (int i = threadIdx.x; i < 18 * 18; i += 256) {
            int ly = i / 18, lx = i % 18;
            int gy = by * 16 + ly - 1, gx = bx * 16 + lx - 1;
            tile[ly][lx] = (gy >= 0 && gy < HH && gx >= 0 && gx < WW)
                               ? __half2float(ip[gy * WW + gx]) : 0.f;
        }
        __syncthreads();
        const float* wp = &ws[c * 9];
        #pragma unroll
        for (int ky = 0; ky < 3; ky++)
            #pragma unroll
            for (int kx = 0; kx < 3; kx++)
                acc = fmaf(wp[ky * 3 + kx], tile[ty + ky][tx + kx], acc);
        __syncthreads();
    }
    int oy = by * 16 + ty, ox = bx * 16 + tx;
    gatep[(size_t)cs * NTOK + (size_t)b * HWH + oy * WW + ox] = acc;
}

// ---------------- final: out = x2 + y4 * sigmoid(sum partials + b) ------------
__global__ __launch_bounds__(256) void final_kernel(
    const float* __restrict__ x2, const __half* __restrict__ y4,
    const float* __restrict__ gatep, const float* __restrict__ b_sa,
    float* __restrict__ out)
{
    int i4 = blockIdx.x * 256 + threadIdx.x;
    int elem = i4 * 4;
    int b = elem / (CC * HWH);
    int p = elem % HWH;
    float4 a = ((const float4*)x2)[i4];
    const __half2* y2 = (const __half2*)y4;
    float2 ya = __half22float2(y2[2 * i4]);
    float2 yb = __half22float2(y2[2 * i4 + 1]);
    size_t gp = (size_t)b * HWH + p;
    float4 s0 = *(const float4*)(gatep + gp);
    float4 s1 = *(const float4*)(gatep + NTOK + gp);
    float4 s2 = *(const float4*)(gatep + 2 * (size_t)NTOK + gp);
    float4 s3 = *(const float4*)(gatep + 3 * (size_t)NTOK + gp);
    float bs = b_sa[0];
    float g0 = 1.0f / (1.0f + expf(-(s0.x + s1.x + s2.x + s3.x + bs)));
    float g1 = 1.0f / (1.0f + expf(-(s0.y + s1.y + s2.y + s3.y + bs)));
    float g2 = 1.0f / (1.0f + expf(-(s0.z + s1.z + s2.z + s3.z + bs)));
    float g3 = 1.0f / (1.0f + expf(-(s0.w + s1.w + s2.w + s3.w + bs)));
    float4 r;
    r.x = a.x + ya.x * g0;
    r.y = a.y + ya.y * g1;
    r.z = a.z + yb.x * g2;
    r.w = a.w + yb.y * g3;
    ((float4*)out)[i4] = r;
}

// =============================================================================
extern "C" void kernel_launch(void* const* d_in, const int* in_sizes, int n_in,
                              void* d_out, int out_size)
{
    const float* x      = (const float*)d_in[0];
    const float* g1     = (const float*)d_in[1];
    const float* b1     = (const float*)d_in[2];
    const float* w_qkv  = (const float*)d_in[3];
    const float* w_dw   = (const float*)d_in[4];
    const float* temp   = (const float*)d_in[5];
    const float* w_head = (const float*)d_in[6];
    const float* w_proj = (const float*)d_in[7];
    const float* g2     = (const float*)d_in[8];
    const float* b2     = (const float*)d_in[9];
    const float* w_fc1  = (const float*)d_in[10];
    const float* b_fc1  = (const float*)d_in[11];
    const float* w_fc2  = (const float*)d_in[12];
    const float* b_fc2  = (const float*)d_in[13];
    const float* w_sa   = (const float*)d_in[14];
    const float* b_sa   = (const float*)d_in[15];
    float* out = (float*)d_out;

    float *p_x1, *p_invn, *p_part, *p_attn, *p_x2, *p_gatep;
    __half *p_x1s, *p_qkv1, *p_qkv2, *p_avs, *p_xns, *p_h1s, *p_y4,
           *p_wq, *p_wp, *p_w1, *p_w2;
    cudaGetSymbolAddress((void**)&p_x1,   g_x1);
    cudaGetSymbolAddress((void**)&p_x1s,  g_x1s);
    cudaGetSymbolAddress((void**)&p_qkv1, g_qkv1);
    cudaGetSymbolAddress((void**)&p_qkv2, g_qkv2);
    cudaGetSymbolAddress((void**)&p_invn, g_invn);
    cudaGetSymbolAddress((void**)&p_part, g_part);
    cudaGetSymbolAddress((void**)&p_attn, g_attn);
    cudaGetSymbolAddress((void**)&p_avs,  g_avs);
    cudaGetSymbolAddress((void**)&p_x2,   g_x2);
    cudaGetSymbolAddress((void**)&p_xns,  g_xns);
    cudaGetSymbolAddress((void**)&p_h1s,  g_h1s);
    cudaGetSymbolAddress((void**)&p_y4,   g_y4);
    cudaGetSymbolAddress((void**)&p_gatep, g_gatep);
    cudaGetSymbolAddress((void**)&p_wq,   g_wq);
    cudaGetSymbolAddress((void**)&p_wp,   g_wp);
    cudaGetSymbolAddress((void**)&p_w1,   g_w1);
    cudaGetSymbolAddress((void**)&p_w2,   g_w2);

    const int SMEM_G = 76800;
    cudaFuncSetAttribute(mma_gemm<192, 0>, cudaFuncAttributeMaxDynamicSharedMemorySize, SMEM_G);
    cudaFuncSetAttribute(mma_gemm<192, 1>, cudaFuncAttributeMaxDynamicSharedMemorySize, SMEM_G);
    cudaFuncSetAttribute(mma_gemm<192, 3>, cudaFuncAttributeMaxDynamicSharedMemorySize, SMEM_G);
    cudaFuncSetAttribute(mma_gemm<384, 2>, cudaFuncAttributeMaxDynamicSharedMemorySize, SMEM_G);

    // weight prep (tiny)
    prep_w<<<(C3 * CC + 255) / 256, 256>>>(w_qkv, p_wq, C3 * CC);
    prep_w<<<(CC * CC + 255) / 256, 256>>>(w_proj, p_wp, CC * CC);
    prep_w<<<(HID * CC + 255) / 256, 256>>>(w_fc1, p_w1, HID * CC);
    prep_w<<<(CC * HID + 255) / 256, 256>>>(w_fc2, p_w2, CC * HID);

    // 1) LN1: x -> x1 (f32 channel-major, residual) + x1s (fp16 token-major)
    ln_split<true><<<dim3(HWH / 32, BB), 256>>>(x, g1, b1, p_x1, p_x1s);

    // 2) qkv GEMM -> qkv1 fp16 channel-major (3 N-tiles of 192)
    mma_gemm<192, 0><<<dim3(NTOK / 128, 3), 256, SMEM_G>>>(
        p_x1s, p_wq, nullptr, nullptr, nullptr, p_qkv1, nullptr, C3, 0);

    // 3) depthwise 3x3 (fp16 in/out)
    dwconv_kernel<<<dim3(HWH / 256, BB * C3), 256>>>(p_qkv1, w_dw, p_qkv2);

    // 4-7) attention path (fp16 qkv2)
    rownorm_kernel<<<BB * 2 * CC, 256>>>(p_qkv2, p_invn);
    qk_kernel<<<dim3(BB * HEADS, NSPLIT), 256>>>(p_qkv2, p_invn, temp, p_part);
    headconv_softmax_kernel<<<BB, 256>>>(p_part, w_head, p_attn);
    av_kernel<<<dim3(HWH / 256, BB * HEADS), 256>>>(p_attn, p_qkv2, p_avs);

    // 8) proj GEMM + residual x1 -> x2 (f32)
    mma_gemm<192, 3><<<dim3(NTOK / 128, 1), 256, SMEM_G>>>(
        p_avs, p_wp, nullptr, p_x1, p_x2, nullptr, nullptr, CC, 0);

    // 9) LN2: x2 -> xns (fp16 token-major only)
    ln_split<false><<<dim3(HWH / 32, BB), 256>>>(p_x2, g2, b2, nullptr, p_xns);

    // 10) fc1 GEMM + bias + gelu -> h1s fp16 token-major (2 N-tiles)
    mma_gemm<192, 1><<<dim3(NTOK / 128, 2), 256, SMEM_G>>>(
        p_xns, p_w1, b_fc1, nullptr, nullptr, nullptr, p_h1s, 0, HID);

    // 11) fc2 GEMM (K=384) + bias + gelu -> y4 fp16 channel-major
    mma_gemm<384, 2><<<dim3(NTOK / 128, 1), 256, SMEM_G>>>(
        p_h1s, p_w2, b_fc2, nullptr, nullptr, p_y4, nullptr, CC, 0);

    // 12) gate partials (4-way channel split), 13) final combine
    gate_kernel<<<BB * 64 * 4, 256>>>(p_y4, w_sa, p_gatep);
    final_kernel<<<(BB * CC * HWH / 4) / 256, 256>>>(p_x2, p_y4, p_gatep, b_sa, out);

    (void)in_sizes; (void)n_in; (void)out_size;
}

// round 12
// speedup vs baseline: 2.1153x; 1.0753x over previous
#include <cuda_runtime.h>
#include <cuda_fp16.h>
#include <math.h>
#include <stdint.h>

#define BB 4
#define CC 192
#define HH 128
#define WW 128
#define HWH (HH*WW)          // 16384
#define C3 576
#define HID 384
#define HEADS 6
#define CP 32
#define NSPLIT 16
#define NTOK (BB*HWH)        // 65536

// ---------------- scratch (device globals; allocation-free) -------------------
__device__ float  g_x1  [(size_t)BB*CC*HWH];
__device__ __half g_x1s [(size_t)NTOK*CC];
__device__ __half g_qkv1[(size_t)BB*C3*HWH];
__device__ __half g_qkv2[(size_t)BB*C3*HWH];
__device__ float  g_invn[BB*2*CC];
__device__ float  g_part[(size_t)NSPLIT*BB*HEADS*CP*CP];
__device__ float  g_attn[BB*HEADS*CP*CP];
__device__ __half g_avs [(size_t)NTOK*CC];
__device__ float  g_x2  [(size_t)BB*CC*HWH];
__device__ __half g_xns [(size_t)NTOK*CC];
__device__ __half g_h1s [(size_t)NTOK*HID];
__device__ __half g_y4  [(size_t)BB*CC*HWH];
__device__ float  g_gatep[(size_t)4*NTOK];
__device__ __half g_wq  [(size_t)C3 *CC];
__device__ __half g_wp  [(size_t)CC *CC];
__device__ __half g_w1  [(size_t)HID*CC];
__device__ __half g_w2  [(size_t)CC *HID];

// ---------------- small helpers ----------------------------------------------
__device__ __forceinline__ float gelu_exact(float x) {
    return 0.5f * x * (1.0f + erff(x * 0.70710678118654752f));
}
__device__ __forceinline__ uint32_t smem_u32(const void* p) {
    uint32_t a;
    asm("{ .reg .u64 t; cvta.to.shared.u64 t, %1; cvt.u32.u64 %0, t; }"
        : "=r"(a) : "l"(p));
    return a;
}
__device__ __forceinline__ void cpa16(uint32_t dst, const void* src) {
    asm volatile("cp.async.cg.shared.global [%0], [%1], 16;" :: "r"(dst), "l"(src) : "memory");
}
__device__ __forceinline__ void mma16816(float* c, const uint32_t* a, const uint32_t* b) {
    asm volatile(
        "mma.sync.aligned.m16n8k16.row.col.f32.f16.f16.f32 "
        "{%0,%1,%2,%3}, {%4,%5,%6,%7}, {%8,%9}, {%0,%1,%2,%3};"
        : "+f"(c[0]), "+f"(c[1]), "+f"(c[2]), "+f"(c[3])
        : "r"(a[0]), "r"(a[1]), "r"(a[2]), "r"(a[3]), "r"(b[0]), "r"(b[1]));
}
#define LDMX4(r, addr)                                                          \
    asm volatile("ldmatrix.sync.aligned.m8n8.x4.shared.b16 {%0,%1,%2,%3}, [%4];" \
        : "=r"((r)[0]), "=r"((r)[1]), "=r"((r)[2]), "=r"((r)[3]) : "r"(addr))
__device__ __forceinline__ uint32_t packh2(float a, float b) {
    __half2 h = __floats2half2_rn(a, b);
    return *(uint32_t*)&h;
}

// ---------------- weight prep: all four weights, one launch -------------------
#define NWQ (C3*CC)
#define NWP (CC*CC)
#define NW1 (HID*CC)
#define NW2 (CC*HID)
__global__ void prep_all(const float* __restrict__ s0, const float* __restrict__ s1,
                         const float* __restrict__ s2, const float* __restrict__ s3,
                         __half* __restrict__ d0, __half* __restrict__ d1,
                         __half* __restrict__ d2, __half* __restrict__ d3)
{
    int i = blockIdx.x * 256 + threadIdx.x;
    if (i < NWQ) { d0[i] = __float2half(s0[i]); return; }
    i -= NWQ;
    if (i < NWP) { d1[i] = __float2half(s1[i]); return; }
    i -= NWP;
    if (i < NW1) { d2[i] = __float2half(s2[i]); return; }
    i -= NW1;
    if (i < NW2) { d3[i] = __float2half(s3[i]); }
}

// ======================= warp-MMA fp16 GEMM (128 x 192 tile) ==================
// D[128 tok, 192 nch] = A[tok,K](fp16) x W[nch,K](fp16), fp32 accum.
// EPI 0: fp16 channel-major    EPI 1: +bias,gelu -> fp16 token-major
// EPI 2: +bias,gelu -> fp16 channel-major
// EPI 4: +res(f32) -> f32 channel-major (x2) AND fused LayerNorm -> fp16
//        token-major (xns). Requires grid.y==1 (all 192 channels in CTA).
// Dynamic smem 76800 B: 3-stage A bufs 3x10240 + B bufs 3x15360 (AST=40 halves
// = 80 B stride, 16B-aligned, ldmatrix conflict-free: groups 5r mod 8 distinct).
template<int K, int EPI>
__global__ __launch_bounds__(256) void mma_gemm(
    const __half* __restrict__ Ag_, const __half* __restrict__ Wp,
    const float* __restrict__ bias, const float* __restrict__ res,
    const float* __restrict__ gamv, const float* __restrict__ betv,
    float* __restrict__ outF, __half* __restrict__ outH,
    __half* __restrict__ outS, int outC, int nRowW)
{
    constexpr int NCH = K / 32;
    constexpr int AST = 40;
    extern __shared__ __align__(16) char sm[];
    const uint32_t smb = smem_u32(sm);
    const uint32_t sA[3] = { smb, smb + 10240, smb + 20480 };
    const uint32_t sB[3] = { smb + 30720, smb + 46080, smb + 61440 };
    float (*Cs)[50] = (float(*)[50])sm;            // 25600 B
    __half* tileH = (__half*)(sm + 25600);         // 128 x 194 halves = 49664 B

    const int tid = threadIdx.x;
    const int wid = tid >> 5, lane = tid & 31;
    const int g = lane >> 2, t2 = (lane & 3) * 2;
    const int wm = wid & 1, wn = wid >> 1;        // warp grid: 2 (M) x 4 (N)
    const size_t tok0 = (size_t)blockIdx.x * 128;
    const int n0 = blockIdx.y * 192;
    const char* Agc = (const char*)(Ag_ + tok0 * K);
    const char* Bgc = (const char*)(Wp + (size_t)n0 * K);

    const uint32_t a_lrow = (uint32_t)(wm * 64 + (lane & 15)) * (AST * 2) + ((lane >> 4) << 4);
    const uint32_t b_lrow = (uint32_t)(wn * 48 + (lane & 7) + ((lane >> 4) << 3)) * (AST * 2)
                          + (((lane >> 3) & 1) << 4);

    float acc[4][6][4];
    #pragma unroll
    for (int mi = 0; mi < 4; mi++)
        #pragma unroll
        for (int ni = 0; ni < 6; ni++)
            #pragma unroll
            for (int q = 0; q < 4; q++) acc[mi][ni][q] = 0.f;

    auto issue = [&](int kc, int buf) {
        const char* As = Agc + kc * 64;          // 32 halves = 64 B
        const char* Bs = Bgc + kc * 64;
        #pragma unroll
        for (int i = 0; i < 2; i++) {            // A: 128 rows x 4 x 16B
            int v = tid + i * 256;
            int r = v >> 2, j = v & 3;
            cpa16(sA[buf] + r * (AST * 2) + j * 16, As + (size_t)r * (2 * K) + j * 16);
        }
        #pragma unroll
        for (int i = 0; i < 3; i++) {            // B: 192 rows x 4 x 16B
            int v = tid + i * 256;
            int r = v >> 2, j = v & 3;
            cpa16(sB[buf] + r * (AST * 2) + j * 16, Bs + (size_t)r * (2 * K) + j * 16);
        }
        asm volatile("cp.async.commit_group;" ::: "memory");
    };

    issue(0, 0);
    issue(1, 1);
    for (int i = 0; i < NCH; i++) {
        int cb = i % 3;
        if (i + 2 < NCH) {
            issue(i + 2, (i + 2) % 3);
            asm volatile("cp.async.wait_group 2;" ::: "memory");
        } else if (i + 1 < NCH) {
            asm volatile("cp.async.wait_group 1;" ::: "memory");
        } else {
            asm volatile("cp.async.wait_group 0;" ::: "memory");
        }
        __syncthreads();
        #pragma unroll
        for (int ks = 0; ks < 2; ks++) {
            uint32_t af[4][4], bfr[6][2];
            #pragma unroll
            for (int mi = 0; mi < 4; mi++) {
                uint32_t ad = sA[cb] + a_lrow + mi * 16 * (AST * 2) + ks * 32;
                LDMX4(af[mi], ad);
            }
            #pragma unroll
            for (int p = 0; p < 3; p++) {
                uint32_t r4[4];
                uint32_t bd = sB[cb] + b_lrow + p * 16 * (AST * 2) + ks * 32;
                LDMX4(r4, bd);
                bfr[2 * p][0] = r4[0]; bfr[2 * p][1] = r4[1];
                bfr[2 * p + 1][0] = r4[2]; bfr[2 * p + 1][1] = r4[3];
            }
            #pragma unroll
            for (int mi = 0; mi < 4; mi++)
                #pragma unroll
                for (int ni = 0; ni < 6; ni++)
                    mma16816(acc[mi][ni], af[mi], bfr[ni]);
        }
        __syncthreads();
    }

    // -------- epilogue: 4 slabs of 48 channels, staged through smem ----------
    const int bq = (int)(tok0 >> 14);
    const int tl0 = (int)(tok0 & 16383);
    for (int s = 0; s < 4; s++) {
        if (wn == s) {
            #pragma unroll
            for (int mi = 0; mi < 4; mi++)
                #pragma unroll
                for (int ni = 0; ni < 6; ni++) {
                    int m = wm * 64 + mi * 16 + g;
                    int n = ni * 8 + t2;
                    Cs[m][n]         = acc[mi][ni][0];
                    Cs[m][n + 1]     = acc[mi][ni][1];
                    Cs[m + 8][n]     = acc[mi][ni][2];
                    Cs[m + 8][n + 1] = acc[mi][ni][3];
                }
        }
        __syncthreads();
        const int chb = n0 + s * 48;
        if (EPI == 1) {
            int tokl = tid >> 1, co = (tid & 1) * 24;
            size_t tok = tok0 + tokl;
            uint32_t hp[12];
            #pragma unroll
            for (int j = 0; j < 12; j++) {
                int ch = co + 2 * j;
                float v0 = gelu_exact(Cs[tokl][ch]     + __ldg(&bias[chb + ch]));
                float v1 = gelu_exact(Cs[tokl][ch + 1] + __ldg(&bias[chb + ch + 1]));
                hp[j] = packh2(v0, v1);
            }
            uint4* dh = (uint4*)(outS + tok * nRowW + chb + co);
            #pragma unroll
            for (int q = 0; q < 3; q++) dh[q] = ((uint4*)hp)[q];
        } else {
            #pragma unroll 4
            for (int i = tid; i < 48 * 128; i += 256) {
                int ch = i >> 7, tl_ = i & 127;
                float v = Cs[tl_][ch];
                int chg = chb + ch;
                size_t idx = ((size_t)bq * outC + chg) * HWH + tl0 + tl_;
                if (EPI == 4) {
                    v += res[idx];
                    outF[idx] = v;
                    tileH[tl_ * 194 + chg] = __float2half(v);
                } else {
                    if (EPI == 2) v = gelu_exact(v + __ldg(&bias[chg]));
                    outH[idx] = __float2half(v);
                }
            }
        }
        __syncthreads();
    }

    // -------- EPI 4: fused LayerNorm over the 192 channels held in tileH -----
    if (EPI == 4) {
        if (tid < 128) {
            const __half2* row = (const __half2*)(tileH + tid * 194);
            float s = 0.f, ss = 0.f;
            #pragma unroll 8
            for (int j = 0; j < 96; j++) {
                float2 f = __half22float2(row[j]);
                s += f.x + f.y;
                ss += f.x * f.x + f.y * f.y;
            }
            float m = s * (1.0f / 192.0f);
            float inv = rsqrtf(ss * (1.0f / 192.0f) - m * m + 1e-5f);
            __half* orow = outS + (tok0 + tid) * CC;
            #pragma unroll
            for (int j = 0; j < 24; j++) {       // 24 uint4 = 192 halves
                uint32_t hp[4];
                #pragma unroll
                for (int q = 0; q < 4; q++) {
                    int c = j * 8 + 2 * q;
                    float2 f = __half22float2(row[j * 4 + q]);
                    float v0 = (f.x - m) * inv * __ldg(&gamv[c])     + __ldg(&betv[c]);
                    float v1 = (f.y - m) * inv * __ldg(&gamv[c + 1]) + __ldg(&betv[c + 1]);
                    hp[q] = packh2(v0, v1);
                }
                ((uint4*)orow)[j] = *(uint4*)hp;
            }
        }
    }
}

// ---------------- LayerNorm -> f32 + fp16 token-major (LN1) -------------------
__global__ __launch_bounds__(256) void ln_split(
    const float* __restrict__ x, const float* __restrict__ g,
    const float* __restrict__ bta, float* __restrict__ outF,
    __half* __restrict__ outS)
{
    __shared__ float t[CC][33];
    __shared__ float s_mean[32], s_inv[32];
    const int b = blockIdx.y, p0 = blockIdx.x * 32;
    const int tid = threadIdx.x, w = tid >> 5, l = tid & 31;
    const float* xb = x + (size_t)b * CC * HWH + p0;
    for (int i = tid; i < CC * 32; i += 256) {
        int c = i >> 5, tk = i & 31;
        t[c][tk] = xb[(size_t)c * HWH + tk];
    }
    __syncthreads();
    #pragma unroll
    for (int r = 0; r < 4; r++) {
        int tk = w * 4 + r;
        float s = 0.f, ss = 0.f;
        #pragma unroll
        for (int c = l; c < CC; c += 32) { float v = t[c][tk]; s += v; ss += v * v; }
        #pragma unroll
        for (int o = 16; o; o >>= 1) {
            s  += __shfl_xor_sync(0xFFFFFFFFu, s, o);
            ss += __shfl_xor_sync(0xFFFFFFFFu, ss, o);
        }
        if (l == 0) {
            float m = s * (1.0f / CC);
            s_mean[tk] = m;
            s_inv[tk]  = rsqrtf(ss * (1.0f / CC) - m * m + 1e-5f);
        }
    }
    __syncthreads();
    {
        float* ob = outF + (size_t)b * CC * HWH + p0;
        for (int i = tid; i < CC * 32; i += 256) {
            int c = i >> 5, tk = i & 31;
            ob[(size_t)c * HWH + tk] =
                (t[c][tk] - s_mean[tk]) * s_inv[tk] * __ldg(&g[c]) + __ldg(&bta[c]);
        }
    }
    #pragma unroll
    for (int r = 0; r < 4; r++) {
        int tk = w * 4 + r;
        if (l < 24) {
            size_t tok = (size_t)b * HWH + p0 + tk;
            float m = s_mean[tk], inv = s_inv[tk];
            uint32_t hp[4];
            #pragma unroll
            for (int j = 0; j < 4; j++) {
                int c = l * 8 + 2 * j;
                float v0 = (t[c][tk]     - m) * inv * __ldg(&g[c])     + __ldg(&bta[c]);
                float v1 = (t[c + 1][tk] - m) * inv * __ldg(&g[c + 1]) + __ldg(&bta[c + 1]);
                hp[j] = packh2(v0, v1);
            }
            *(uint4*)(outS + tok * CC + l * 8) = *(uint4*)hp;
        }
    }
}

// ---------------- depthwise 3x3, pad 1 (fp16 in/out, fp32 math) --------------
__global__ __launch_bounds__(256) void dwconv_kernel(
    const __half* __restrict__ in, const float* __restrict__ w,
    __half* __restrict__ out)
{
    int p  = blockIdx.x * 256 + threadIdx.x;
    int bc = blockIdx.y;
    int c  = bc % C3;
    int y  = p >> 7, x0 = p & 127;
    const __half* ip = in + (size_t)bc * HWH;
    const float* wp = w + c * 9;
    float acc = 0.f;
    #pragma unroll
    for (int ky = 0; ky < 3; ky++) {
        int yy = y + ky - 1;
        if (yy < 0 || yy >= HH) continue;
        #pragma unroll
        for (int kx = 0; kx < 3; kx++) {
            int xx = x0 + kx - 1;
            if (xx < 0 || xx >= WW) continue;
            acc += wp[ky * 3 + kx] * __half2float(ip[yy * WW + xx]);
        }
    }
    out[(size_t)bc * HWH + p] = __float2half(acc);
}

// ---------------- q,k inverse L2 norms (fp16 rows) -----------------------------
__global__ __launch_bounds__(256) void rownorm_kernel(
    const __half* __restrict__ qkv, float* __restrict__ invn)
{
    int b = blockIdx.x / 384;
    int c = blockIdx.x % 384;
    const __half2* row = (const __half2*)(qkv + ((size_t)b * C3 + c) * HWH);
    float ss = 0.f;
    for (int i = threadIdx.x; i < HWH / 2; i += 256) {
        float2 f = __half22float2(row[i]);
        ss += f.x * f.x + f.y * f.y;
    }
    __shared__ float red[256];
    red[threadIdx.x] = ss;
    __syncthreads();
    for (int s = 128; s > 0; s >>= 1) {
        if (threadIdx.x < s) red[threadIdx.x] += red[threadIdx.x + s];
        __syncthreads();
    }
    if (threadIdx.x == 0)
        invn[blockIdx.x] = 1.0f / fmaxf(sqrtf(red[0]), 1e-12f);
}

// ---------------- attn partial = q k^T over split-n (fp16 input) --------------
__global__ __launch_bounds__(256) void qk_kernel(
    const __half* __restrict__ qkv, const float* __restrict__ invn,
    const float* __restrict__ temp, float* __restrict__ part)
{
    int bh = blockIdx.x;
    int b = bh / HEADS, hd = bh % HEADS;
    const __half2* q2 = (const __half2*)(qkv + ((size_t)b * C3 + hd * CP) * HWH);
    const __half2* k2 = (const __half2*)(qkv + ((size_t)b * C3 + CC + hd * CP) * HWH);
    __shared__ float Qs[32][65];
    __shared__ float Ks[32][65];
    const int n0 = blockIdx.y * (HWH / NSPLIT);
    float acc[4] = {0.f, 0.f, 0.f, 0.f};
    const int c = threadIdx.x & 31;
    const int dbase = (threadIdx.x >> 5) * 4;
    for (int t = 0; t < HWH / NSPLIT; t += 64) {
        int base2 = (n0 + t) >> 1;
        for (int i = threadIdx.x; i < 32 * 32; i += 256) {
            int r = i >> 5, c2 = i & 31;
            float2 fq = __half22float2(q2[(size_t)r * (HWH / 2) + base2 + c2]);
            float2 fk = __half22float2(k2[(size_t)r * (HWH / 2) + base2 + c2]);
            Qs[r][2 * c2] = fq.x; Qs[r][2 * c2 + 1] = fq.y;
            Ks[r][2 * c2] = fk.x; Ks[r][2 * c2 + 1] = fk.y;
        }
        __syncthreads();
        #pragma unroll 8
        for (int n = 0; n < 64; n++) {
            float qv = Qs[c][n];
            acc[0] = fmaf(qv, Ks[dbase + 0][n], acc[0]);
            acc[1] = fmaf(qv, Ks[dbase + 1][n], acc[1]);
            acc[2] = fmaf(qv, Ks[dbase + 2][n], acc[2]);
            acc[3] = fmaf(qv, Ks[dbase + 3][n], acc[3]);
        }
        __syncthreads();
    }
    float iq = invn[b * 384 + hd * CP + c];
    float tp = temp[hd];
    #pragma unroll
    for (int j = 0; j < 4; j++) {
        int d = dbase + j;
        float ik = invn[b * 384 + CC + hd * CP + d];
        part[((size_t)blockIdx.y * (BB * HEADS) + bh) * 1024 + c * 32 + d]
            = acc[j] * iq * ik * tp;
    }
}

// ---------------- reduce + 3x3 head conv + softmax (1024 threads) -------------
__global__ __launch_bounds__(1024) void headconv_softmax_kernel(
    const float* __restrict__ part, const float* __restrict__ w_head,
    float* __restrict__ attnF)
{
    int b = blockIdx.x;
    __shared__ float A[HEADS * 1024];
    __shared__ float wsh[HEADS * HEADS * 9];
    int tid = threadIdx.x;
    if (tid < HEADS * HEADS * 9) wsh[tid] = w_head[tid];
    for (int i = tid; i < HEADS * 1024; i += 1024) {
        int hd = i >> 10, rest = i & 1023;
        float s = 0.f;
        #pragma unroll
        for (int sp = 0; sp < NSPLIT; sp++)
            s += part[((size_t)sp * (BB * HEADS) + b * HEADS + hd) * 1024 + rest];
        A[i] = s;
    }
    __syncthreads();
    float cv[6];
    #pragma unroll
    for (int r = 0; r < 6; r++) {
        int i  = tid * 6 + r;
        int ho = i >> 10;
        int yx = i & 1023;
        int y = yx >> 5, x = yx & 31;
        float s = 0.f;
        for (int hi = 0; hi < HEADS; hi++) {
            const float* Ah = &A[hi * 1024];
            #pragma unroll
            for (int ky = 0; ky < 3; ky++) {
                int yy = y + ky - 1;
                if (yy < 0 || yy > 31) continue;
                #pragma unroll
                for (int kx = 0; kx < 3; kx++) {
                    int xx = x + kx - 1;
                    if (xx < 0 || xx > 31) continue;
                    s += wsh[((ho * HEADS + hi) * 3 + ky) * 3 + kx] * Ah[yy * 32 + xx];
                }
            }
        }
        cv[r] = s;
    }
    __syncthreads();
    #pragma unroll
    for (int r = 0; r < 6; r++) A[tid * 6 + r] = cv[r];
    __syncthreads();
    if (tid < HEADS * 32) {
        float* row = &A[tid * 32];
        float mx = -1e30f;
        for (int j = 0; j < 32; j++) mx = fmaxf(mx, row[j]);
        float sum = 0.f, e[32];
        for (int j = 0; j < 32; j++) { e[j] = expf(row[j] - mx); sum += e[j]; }
        float inv = 1.0f / sum;
        float* o = attnF + (size_t)b * (HEADS * 1024) + tid * 32;
        for (int j = 0; j < 32; j++) o[j] = e[j] * inv;
    }
}

// ---------------- out = attn @ v -> fp16 token-major ---------------------------
__global__ __launch_bounds__(256) void av_kernel(
    const float* __restrict__ attn, const __half* __restrict__ qkv,
    __half* __restrict__ avs)
{
    int bh = blockIdx.y;
    int b = bh / HEADS, hd = bh % HEADS;
    __shared__ float As[32][32];
    for (int i = threadIdx.x; i < 1024; i += 256)
        ((float*)As)[i] = attn[(size_t)bh * 1024 + i];
    __syncthreads();
    int n = blockIdx.x * 256 + threadIdx.x;
    const __half* v = qkv + ((size_t)b * C3 + 2 * CC + hd * CP) * HWH + n;
    float vv[32];
    #pragma unroll
    for (int d = 0; d < 32; d++) vv[d] = __half2float(v[(size_t)d * HWH]);
    uint32_t hp[16];
    #pragma unroll
    for (int c2 = 0; c2 < 16; c2++) {
        float s0 = 0.f, s1 = 0.f;
        #pragma unroll
        for (int d = 0; d < 32; d++) {
            s0 = fmaf(As[2 * c2][d], vv[d], s0);
            s1 = fmaf(As[2 * c2 + 1][d], vv[d], s1);
        }
        hp[c2] = packh2(s0, s1);
    }
    size_t tok = (size_t)b * HWH + n;
    uint4* dh = (uint4*)(avs + tok * CC + hd * 32);
    #pragma unroll
    for (int q = 0; q < 4; q++) dh[q] = ((uint4*)hp)[q];
}

// ---------------- spatial gate partials: 48 channels per block ----------------
__global__ __launch_bounds__(256) void gate_kernel(
    const __half* __restrict__ y4, const float* __restrict__ w_sa,
    float* __restrict__ gatep)
{
    __shared__ float tile[18][18];
    __shared__ float ws[48 * 9];
    int bx = blockIdx.x & 7;
    int by = (blockIdx.x >> 3) & 7;
    int cs = (blockIdx.x >> 6) & 3;
    int b  = blockIdx.x >> 8;
    int tx = threadIdx.x & 15, ty = threadIdx.x >> 4;
    for (int i = threadIdx.x; i < 48 * 9; i += 256) ws[i] = w_sa[cs * 48 * 9 + i];
    float acc = 0.f;
    for (int c = 0; c < 48; c++) {
        const __half* ip = y4 + ((size_t)b * CC + cs * 48 + c) * HWH;
        for (int i = threadIdx.x; i < 18 * 18; i += 256) {
            int ly = i / 18, lx = i % 18;
            int gy = by * 16 + ly - 1, gx = bx * 16 + lx - 1;
            tile[ly][lx] = (gy >= 0 && gy < HH && gx >= 0 && gx < WW)
                               ? __half2float(ip[gy * WW + gx]) : 0.f;
        }
        __syncthreads();
        const float* wp = &ws[c * 9];
        #pragma unroll
        for (int ky = 0; ky < 3; ky++)
            #pragma unroll
            for (int kx = 0; kx < 3; kx++)
                acc = fmaf(wp[ky * 3 + kx], tile[ty + ky][tx + kx], acc);
        __syncthreads();
    }
    int oy = by * 16 + ty, ox = bx * 16 + tx;
    gatep[(size_t)cs * NTOK + (size_t)b * HWH + oy * WW + ox] = acc;
}

// ---------------- final: out = x2 + y4 * sigmoid(sum partials + b) ------------
__global__ __launch_bounds__(256) void final_kernel(
    const float* __restrict__ x2, const __half* __restrict__ y4,
    const float* __restrict__ gatep, const float* __restrict__ b_sa,
    float* __restrict__ out)
{
    int i4 = blockIdx.x * 256 + threadIdx.x;
    int elem = i4 * 4;
    int b = elem / (CC * HWH);
    int p = elem % HWH;
    float4 a = ((const float4*)x2)[i4];
    const __half2* y2 = (const __half2*)y4;
    float2 ya = __half22float2(y2[2 * i4]);
    float2 yb = __half22float2(y2[2 * i4 + 1]);
    size_t gp = (size_t)b * HWH + p;
    float4 s0 = *(const float4*)(gatep + gp);
    float4 s1 = *(const float4*)(gatep + NTOK + gp);
    float4 s2 = *(const float4*)(gatep + 2 * (size_t)NTOK + gp);
    float4 s3 = *(const float4*)(gatep + 3 * (size_t)NTOK + gp);
    float bs = b_sa[0];
    float g0 = 1.0f / (1.0f + expf(-(s0.x + s1.x + s2.x + s3.x + bs)));
    float g1 = 1.0f / (1.0f + expf(-(s0.y + s1.y + s2.y + s3.y + bs)));
    float g2 = 1.0f / (1.0f + expf(-(s0.z + s1.z + s2.z + s3.z + bs)));
    float g3 = 1.0f / (1.0f + expf(-(s0.w + s1.w + s2.w + s3.w + bs)));
    float4 r;
    r.x = a.x + ya.x * g0;
    r.y = a.y + ya.y * g1;
    r.z = a.z + yb.x * g2;
    r.w = a.w + yb.y * g3;
    ((float4*)out)[i4] = r;
}

// =============================================================================
extern "C" void kernel_launch(void* const* d_in, const int* in_sizes, int n_in,
                              void* d_out, int out_size)
{
    const float* x      = (const float*)d_in[0];
    const float* g1     = (const float*)d_in[1];
    const float* b1     = (const float*)d_in[2];
    const float* w_qkv  = (const float*)d_in[3];
    const float* w_dw   = (const float*)d_in[4];
    const float* temp   = (const float*)d_in[5];
    const float* w_head = (const float*)d_in[6];
    const float* w_proj = (const float*)d_in[7];
    const float* g2     = (const float*)d_in[8];
    const float* b2     = (const float*)d_in[9];
    const float* w_fc1  = (const float*)d_in[10];
    const float* b_fc1  = (const float*)d_in[11];
    const float* w_fc2  = (const float*)d_in[12];
    const float* b_fc2  = (const float*)d_in[13];
    const float* w_sa   = (const float*)d_in[14];
    const float* b_sa   = (const float*)d_in[15];
    float* out = (float*)d_out;

    float *p_x1, *p_invn, *p_part, *p_attn, *p_x2, *p_gatep;
    __half *p_x1s, *p_qkv1, *p_qkv2, *p_avs, *p_xns, *p_h1s, *p_y4,
           *p_wq, *p_wp, *p_w1, *p_w2;
    cudaGetSymbolAddress((void**)&p_x1,   g_x1);
    cudaGetSymbolAddress((void**)&p_x1s,  g_x1s);
    cudaGetSymbolAddress((void**)&p_qkv1, g_qkv1);
    cudaGetSymbolAddress((void**)&p_qkv2, g_qkv2);
    cudaGetSymbolAddress((void**)&p_invn, g_invn);
    cudaGetSymbolAddress((void**)&p_part, g_part);
    cudaGetSymbolAddress((void**)&p_attn, g_attn);
    cudaGetSymbolAddress((void**)&p_avs,  g_avs);
    cudaGetSymbolAddress((void**)&p_x2,   g_x2);
    cudaGetSymbolAddress((void**)&p_xns,  g_xns);
    cudaGetSymbolAddress((void**)&p_h1s,  g_h1s);
    cudaGetSymbolAddress((void**)&p_y4,   g_y4);
    cudaGetSymbolAddress((void**)&p_gatep, g_gatep);
    cudaGetSymbolAddress((void**)&p_wq,   g_wq);
    cudaGetSymbolAddress((void**)&p_wp,   g_wp);
    cudaGetSymbolAddress((void**)&p_w1,   g_w1);
    cudaGetSymbolAddress((void**)&p_w2,   g_w2);

    const int SMEM_G = 76800;
    cudaFuncSetAttribute(mma_gemm<192, 0>, cudaFuncAttributeMaxDynamicSharedMemorySize, SMEM_G);
    cudaFuncSetAttribute(mma_gemm<192, 1>, cudaFuncAttributeMaxDynamicSharedMemorySize, SMEM_G);
    cudaFuncSetAttribute(mma_gemm<192, 4>, cudaFuncAttributeMaxDynamicSharedMemorySize, SMEM_G);
    cudaFuncSetAttribute(mma_gemm<384, 2>, cudaFuncAttributeMaxDynamicSharedMemorySize, SMEM_G);

    // weight prep (single launch)
    prep_all<<<(NWQ + NWP + NW1 + NW2 + 255) / 256, 256>>>(
        w_qkv, w_proj, w_fc1, w_fc2, p_wq, p_wp, p_w1, p_w2);

    // 1) LN1: x -> x1 (f32 channel-major, residual) + x1s (fp16 token-major)
    ln_split<<<dim3(HWH / 32, BB), 256>>>(x, g1, b1, p_x1, p_x1s);

    // 2) qkv GEMM -> qkv1 fp16 channel-major (3 N-tiles of 192)
    mma_gemm<192, 0><<<dim3(NTOK / 128, 3), 256, SMEM_G>>>(
        p_x1s, p_wq, nullptr, nullptr, nullptr, nullptr, nullptr, p_qkv1, nullptr, C3, 0);

    // 3) depthwise 3x3 (fp16 in/out)
    dwconv_kernel<<<dim3(HWH / 256, BB * C3), 256>>>(p_qkv1, w_dw, p_qkv2);

    // 4-7) attention path (fp16 qkv2)
    rownorm_kernel<<<BB * 2 * CC, 256>>>(p_qkv2, p_invn);
    qk_kernel<<<dim3(BB * HEADS, NSPLIT), 256>>>(p_qkv2, p_invn, temp, p_part);
    headconv_softmax_kernel<<<BB, 1024>>>(p_part, w_head, p_attn);
    av_kernel<<<dim3(HWH / 256, BB * HEADS), 256>>>(p_attn, p_qkv2, p_avs);

    // 8) proj GEMM + residual -> x2 (f32) + fused LN2 -> xns (fp16)
    mma_gemm<192, 4><<<dim3(NTOK / 128, 1), 256, SMEM_G>>>(
        p_avs, p_wp, nullptr, p_x1, g2, b2, p_x2, nullptr, p_xns, CC, 0);

    // 10) fc1 GEMM + bias + gelu -> h1s fp16 token-major (2 N-tiles)
    mma_gemm<192, 1><<<dim3(NTOK / 128, 2), 256, SMEM_G>>>(
        p_xns, p_w1, b_fc1, nullptr, nullptr, nullptr, nullptr, nullptr, p_h1s, 0, HID);

    // 11) fc2 GEMM (K=384) + bias + gelu -> y4 fp16 channel-major
    mma_gemm<384, 2><<<dim3(NTOK / 128, 1), 256, SMEM_G>>>(
        p_h1s, p_w2, b_fc2, nullptr, nullptr, nullptr, nullptr, p_y4, nullptr, CC, 0);

    // 12) gate partials (4-way channel split), 13) final combine
    gate_kernel<<<BB * 64 * 4, 256>>>(p_y4, w_sa, p_gatep);
    final_kernel<<<(BB * CC * HWH / 4) / 256, 256>>>(p_x2, p_y4, p_gatep, b_sa, out);

    (void)in_sizes; (void)n_in; (void)out_size;
}